// round 7
// baseline (speedup 1.0000x reference)
#include <cuda_runtime.h>
#include <cstdint>
#include <cstddef>

#define Bc 64
#define Sc 512
#define Hc 1024
#define Vc 32000
#define SB (Sc * Bc)

// ---------------- scratch (device globals, no allocation) ----------------
__device__ float g_hWh[Bc * Hc];         // reduced: [b][h] hidden@W_h^T + attn_w_b
__device__ float g_hWhp[4 * Bc * Hc];    // split-K partials
__device__ float g_spart[SB * 32];       // 32 partial scores per row r = s*B+b
__device__ float g_x[Bc * 2 * Hc];       // [b][emb ; context]
__device__ float g_gip[4 * Bc * 3 * Hc]; // gi split-K partials [z][b][3H]
__device__ float g_ghp[4 * Bc * 3 * Hc]; // gh split-K partials [z][b][3H]

// ---------------- portable-PTX helpers ----------------
__device__ __forceinline__ uint32_t smem_u32(const void* p) {
    uint32_t a;
    asm("{ .reg .u64 t; cvta.to.shared.u64 t, %1; cvt.u32.u64 %0, t; }"
        : "=r"(a) : "l"(p));
    return a;
}
#define CPA(dst, src) \
    asm volatile("cp.async.cg.shared.global [%0], [%1], 16;" :: "r"(dst), "l"(src))
#define CPCOMMIT() asm volatile("cp.async.commit_group;" ::: "memory")
#define CPWAIT(n)  asm volatile("cp.async.wait_group %0;" :: "n"(n) : "memory")

__device__ __forceinline__ void mma_tf32(float* c, const uint32_t* a, const uint32_t* b) {
    asm volatile(
        "mma.sync.aligned.m16n8k8.row.col.f32.tf32.tf32.f32 "
        "{%0,%1,%2,%3}, {%4,%5,%6,%7}, {%8,%9}, {%0,%1,%2,%3};"
        : "+f"(c[0]), "+f"(c[1]), "+f"(c[2]), "+f"(c[3])
        : "r"(a[0]), "r"(a[1]), "r"(a[2]), "r"(a[3]), "r"(b[0]), "r"(b[1]));
}
__device__ __forceinline__ void split_tf32(float x, uint32_t& hi, uint32_t& lo) {
    uint32_t h = __float_as_uint(x) & 0xFFFFE000u;
    hi = h;
    lo = __float_as_uint(x - __uint_as_float(h));   // exact (same exponent)
}

// ===========================================================================
// Attention score kernel (mma.sync tf32). CTA tile 128x128, warp tile 64x32.
// 4-stage pipeline, K=16 per stage (static buf = ks & 3 via unroll 4),
// lookahead 3 stages, ONE sync per stage. 2 CTAs/SM.
// ===========================================================================
// smem: 4 stages x (A 128x20 + B 128x20 floats) = 81920 B
#define ATT_SMEM 81920

__global__ void __launch_bounds__(256, 2)
attn_score_tc(const float* __restrict__ enc, const float* __restrict__ W,
              const float* __restrict__ vvec)
{
    extern __shared__ float sm[];
    const int tid = threadIdx.x, lane = tid & 31, wid = tid >> 5;
    const int n0 = blockIdx.x * 128, m0 = blockIdx.y * 128;
    const int wm = (wid >> 2) * 64, wn = (wid & 3) * 32;
    const float* Wp = W + Hc;
    const uint32_t sbase = smem_u32(sm);

    float acc[4][4][4] = {};

#define LOAD_STAGE(buf, kk)                                                   \
    do {                                                                      \
        const uint32_t db = sbase + (buf) * 20480u;                           \
        _Pragma("unroll")                                                     \
        for (int i_ = 0; i_ < 2; i_++) {                                      \
            int c_ = i_ * 256 + tid;                                          \
            int row_ = c_ >> 2, kc_ = c_ & 3;                                 \
            CPA(db + (row_ * 20 + kc_ * 4) * 4,                               \
                enc + (size_t)(m0 + row_) * Hc + (kk) + kc_ * 4);             \
            CPA(db + 10240u + (row_ * 20 + kc_ * 4) * 4,                      \
                Wp + (size_t)(n0 + row_) * (2 * Hc) + (kk) + kc_ * 4);        \
        }                                                                     \
        CPCOMMIT();                                                           \
    } while (0)

    LOAD_STAGE(0, 0);
    LOAD_STAGE(1, 16);
    LOAD_STAGE(2, 32);
    const int fr = lane >> 2, fc = lane & 3;

#pragma unroll 4
    for (int ks = 0; ks < 64; ks++) {
        CPWAIT(2);                       // stage ks resident
        __syncthreads();
        if (ks < 61) LOAD_STAGE((ks + 3) & 3, (ks + 3) * 16);
        else         CPCOMMIT();         // empty group keeps cadence
        const float* Sa = sm + (ks & 3) * 5120;
        const float* Sb = Sa + 2560;
#pragma unroll
        for (int kh = 0; kh < 2; kh++) {
            const int k8 = kh * 8;
            uint32_t a[4][4], b[4][2];
#pragma unroll
            for (int mi = 0; mi < 4; mi++) {
                const float* ap = Sa + (wm + 16 * mi + fr) * 20 + k8 + fc;
                a[mi][0] = __float_as_uint(ap[0]);
                a[mi][1] = __float_as_uint(ap[160]);
                a[mi][2] = __float_as_uint(ap[4]);
                a[mi][3] = __float_as_uint(ap[164]);
            }
#pragma unroll
            for (int nj = 0; nj < 4; nj++) {
                const float* bp = Sb + (wn + 8 * nj + fr) * 20 + k8 + fc;
                b[nj][0] = __float_as_uint(bp[0]);
                b[nj][1] = __float_as_uint(bp[4]);
            }
#pragma unroll
            for (int mi = 0; mi < 4; mi++)
#pragma unroll
                for (int nj = 0; nj < 4; nj++)
                    mma_tf32(acc[mi][nj], a[mi], b[nj]);
        }
        // next iteration's sync protects the buffer being refilled
    }
#undef LOAD_STAGE
    __syncthreads();   // all warps done with final stages before overlay

    // ---- epilogue: stage hWh slice (stride 133, conflict-free) + v slice ----
    float* shf = sm;
    float* shv = sm + 64 * 133;
    for (int j = tid; j < 64 * 128; j += 256) {
        int b = j >> 7, c = j & 127;
        shf[b * 133 + c] = g_hWh[b * Hc + n0 + c];
    }
    if (tid < 128) shv[tid] = vvec[n0 + tid];
    __syncthreads();

    const int c2 = (lane & 3) * 2;
    float s[4][2] = {};
#pragma unroll
    for (int mi = 0; mi < 4; mi++) {
        const int R0 = wm + 16 * mi + fr;
        const int b0 = R0 & 63, b1 = (R0 + 8) & 63;
#pragma unroll
        for (int nj = 0; nj < 4; nj++) {
            const int n = wn + 8 * nj + c2;
            const float v0 = shv[n], v1 = shv[n + 1];
            s[mi][0] += tanhf(acc[mi][nj][0] + shf[b0 * 133 + n]) * v0
                      + tanhf(acc[mi][nj][1] + shf[b0 * 133 + n + 1]) * v1;
            s[mi][1] += tanhf(acc[mi][nj][2] + shf[b1 * 133 + n]) * v0
                      + tanhf(acc[mi][nj][3] + shf[b1 * 133 + n + 1]) * v1;
        }
    }
#pragma unroll
    for (int mi = 0; mi < 4; mi++)
#pragma unroll
        for (int h = 0; h < 2; h++) {
            s[mi][h] += __shfl_xor_sync(0xffffffffu, s[mi][h], 1);
            s[mi][h] += __shfl_xor_sync(0xffffffffu, s[mi][h], 2);
        }
    if ((lane & 3) == 0) {
        const int col = blockIdx.x * 4 + (wid & 3);
#pragma unroll
        for (int mi = 0; mi < 4; mi++) {
            const int R0 = wm + 16 * mi + fr;
            g_spart[(size_t)(m0 + R0) * 32 + col]     = s[mi][0];
            g_spart[(size_t)(m0 + R0 + 8) * 32 + col] = s[mi][1];
        }
    }
}

// ===========================================================================
// Exact fp32 SIMT split-K GEMM body (device function).
// Cpart[z*64+n][m0+m] = A[m0+m, zKs:(z+1)Ks] . act[n, zKs:(z+1)Ks]
// ===========================================================================
__device__ __forceinline__ void splitk_body(
    const float* __restrict__ A, int lda,
    const float* __restrict__ act, int ldact,
    float* __restrict__ Cpart, int M, int Ks, int m0, int z)
{
    __shared__ float As[16][68];
    __shared__ float Bs[16][68];
    const int tid = threadIdx.x;

    const int lrow = tid >> 2, lk = (tid & 3) * 4;
    const float* Ap = A + (size_t)(m0 + lrow) * lda + z * Ks + lk;
    const float* Bp = act + (size_t)lrow * ldact + z * Ks + lk;

    const int ty = tid >> 4, tx = tid & 15;
    float acc[4][4] = {};

    for (int k0 = 0; k0 < Ks; k0 += 16) {
        float4 av = *(const float4*)(Ap + k0);
        float4 bv = *(const float4*)(Bp + k0);
        As[lk + 0][lrow] = av.x; As[lk + 1][lrow] = av.y;
        As[lk + 2][lrow] = av.z; As[lk + 3][lrow] = av.w;
        Bs[lk + 0][lrow] = bv.x; Bs[lk + 1][lrow] = bv.y;
        Bs[lk + 2][lrow] = bv.z; Bs[lk + 3][lrow] = bv.w;
        __syncthreads();
#pragma unroll
        for (int k = 0; k < 16; k++) {
            float4 a = *(const float4*)&As[k][ty * 4];
            float4 b = *(const float4*)&Bs[k][tx * 4];
            float ar[4] = {a.x, a.y, a.z, a.w};
            float br[4] = {b.x, b.y, b.z, b.w};
#pragma unroll
            for (int i = 0; i < 4; i++)
#pragma unroll
                for (int j = 0; j < 4; j++)
                    acc[i][j] += ar[i] * br[j];
        }
        __syncthreads();
    }

#pragma unroll
    for (int i = 0; i < 4; i++)
#pragma unroll
        for (int j = 0; j < 4; j++)
            Cpart[(size_t)(z * 64 + tx * 4 + j) * M + m0 + ty * 4 + i] = acc[i][j];
}

// Combined pre-attention split-K launch: hWh partials (bx<16) + gh partials.
__global__ void __launch_bounds__(256)
splitk_pre(const float* __restrict__ attn_w_W, const float* __restrict__ hidden,
           const float* __restrict__ gru_Whh,
           float* __restrict__ hWhp, float* __restrict__ ghp)
{
    const int bx = blockIdx.x, z = blockIdx.z;
    if (bx < 16)
        splitk_body(attn_w_W, 2 * Hc, hidden, Hc, hWhp, Hc, 256, bx * 64, z);
    else
        splitk_body(gru_Whh, Hc, hidden, Hc, ghp, 3 * Hc, 256, (bx - 16) * 64, z);
}

// gi partials (post-context)
__global__ void __launch_bounds__(256)
splitk_gi(const float* __restrict__ gru_Wih, const float* __restrict__ x,
          float* __restrict__ gip)
{
    splitk_body(gru_Wih, 2 * Hc, x, 2 * Hc, gip, 3 * Hc, 512, blockIdx.x * 64, blockIdx.z);
}

// Reduce hWh partials + attn_w_b -> g_hWh
__global__ void __launch_bounds__(256)
hwh_reduce(const float* __restrict__ awb)
{
    const int idx = blockIdx.x * 256 + threadIdx.x;   // 65536
    const int b = idx >> 10, h = idx & 1023;
    float v = awb[h];
#pragma unroll
    for (int z = 0; z < 4; z++) v += g_hWhp[(size_t)(z * 64 + b) * Hc + h];
    g_hWh[idx] = v;
}

// ===========================================================================
// Logits GEMM: 3-term split-tf32 (near-fp32 accuracy on tensor cores).
// ===========================================================================
__global__ void __launch_bounds__(256)
gemm_wact_tc(const float* __restrict__ A, int lda, int K,
             const float* __restrict__ act,
             float* __restrict__ C, int ldc,
             const float* __restrict__ bias)
{
    __shared__ float sm[7680];   // [2 bufs][ A:128x20 | act:64x20 ]
    const int tid = threadIdx.x, lane = tid & 31, wid = tid >> 5;
    const int m0 = blockIdx.x * 128;
    const int wm = (wid & 3) * 32, wn = (wid >> 2) * 32;

    float acc[2][4][4] = {};

    const int lr = tid >> 2, lc = (tid & 3) * 4;
    const float* Ag0 = A + (size_t)(m0 + lr) * lda + lc;
    const float* Ag1 = A + (size_t)(m0 + lr + 64) * lda + lc;
    const float* Cg  = act + (size_t)lr * K + lc;
    const uint32_t sA0 = smem_u32(&sm[lr * 20 + lc]);
    const uint32_t sA1 = smem_u32(&sm[(lr + 64) * 20 + lc]);
    const uint32_t sC0 = smem_u32(&sm[2560 + lr * 20 + lc]);

#define W_LOAD(buf, k0)                                     \
    do {                                                    \
        CPA(sA0 + (buf) * 15360, Ag0 + (k0));               \
        CPA(sA1 + (buf) * 15360, Ag1 + (k0));               \
        CPA(sC0 + (buf) * 15360, Cg + (k0));                \
        CPCOMMIT();                                         \
    } while (0)

    const int NS = K / 16;
    W_LOAD(0, 0);
    const int fr = lane >> 2, fc = lane & 3;

    for (int ks = 0; ks < NS; ks++) {
        const int buf = ks & 1;
        if (ks + 1 < NS) { W_LOAD(buf ^ 1, (ks + 1) * 16); CPWAIT(1); }
        else             { CPWAIT(0); }
        __syncthreads();
        const float* As = &sm[buf * 3840];
        const float* Bs = &sm[buf * 3840 + 2560];
#pragma unroll
        for (int kh = 0; kh < 2; kh++) {
            const int k8 = kh * 8;
            uint32_t ah[2][4], al[2][4], bh[4][2], bl[4][2];
#pragma unroll
            for (int mi = 0; mi < 2; mi++) {
                const float* ap = As + (wm + 16 * mi + fr) * 20 + k8 + fc;
                split_tf32(ap[0],   ah[mi][0], al[mi][0]);
                split_tf32(ap[160], ah[mi][1], al[mi][1]);
                split_tf32(ap[4],   ah[mi][2], al[mi][2]);
                split_tf32(ap[164], ah[mi][3], al[mi][3]);
            }
#pragma unroll
            for (int nj = 0; nj < 4; nj++) {
                const float* bp = Bs + (wn + 8 * nj + fr) * 20 + k8 + fc;
                split_tf32(bp[0], bh[nj][0], bl[nj][0]);
                split_tf32(bp[4], bh[nj][1], bl[nj][1]);
            }
#pragma unroll
            for (int mi = 0; mi < 2; mi++)
#pragma unroll
                for (int nj = 0; nj < 4; nj++) {
                    mma_tf32(acc[mi][nj], ah[mi], bl[nj]);
                    mma_tf32(acc[mi][nj], al[mi], bh[nj]);
                    mma_tf32(acc[mi][nj], ah[mi], bh[nj]);
                }
        }
        __syncthreads();
    }
#undef W_LOAD

    const int c2 = (lane & 3) * 2;
#pragma unroll
    for (int mi = 0; mi < 2; mi++) {
        const int m = m0 + wm + 16 * mi + fr;
        const float bm0 = bias[m], bm1 = bias[m + 8];
#pragma unroll
        for (int nj = 0; nj < 4; nj++) {
            const int n = wn + 8 * nj + c2;
            C[(size_t)n * ldc + m]           = acc[mi][nj][0] + bm0;
            C[(size_t)(n + 1) * ldc + m]     = acc[mi][nj][1] + bm0;
            C[(size_t)n * ldc + m + 8]       = acc[mi][nj][2] + bm1;
            C[(size_t)(n + 1) * ldc + m + 8] = acc[mi][nj][3] + bm1;
        }
    }
}

// ===========================================================================
// Fused: per-b softmax (local recompute) + attn_weights write (kc==0) +
// embedding copy + context. grid (4 k-chunks, 64 b).
// ===========================================================================
__global__ void __launch_bounds__(256)
ctx_fused(const float* __restrict__ enc, const int* __restrict__ input,
          const float* __restrict__ emb, float* __restrict__ wout)
{
    __shared__ float sc[Sc];
    __shared__ float red[256];
    const int kc = blockIdx.x, b = blockIdx.y, tid = threadIdx.x;

    for (int s = tid; s < Sc; s += 256) {
        const float4* p = (const float4*)&g_spart[(size_t)(s * Bc + b) * 32];
        float v = 0.0f;
#pragma unroll
        for (int i = 0; i < 8; i++) {
            float4 q = p[i];
            v += q.x + q.y + q.z + q.w;
        }
        sc[s] = v;
    }
    __syncthreads();

    float m = fmaxf(sc[tid], sc[tid + 256]);
    red[tid] = m;
    __syncthreads();
    for (int st = 128; st > 0; st >>= 1) {
        if (tid < st) red[tid] = fmaxf(red[tid], red[tid + st]);
        __syncthreads();
    }
    float mx = red[0];
    __syncthreads();

    float e0 = expf(sc[tid] - mx);
    float e1 = expf(sc[tid + 256] - mx);
    red[tid] = e0 + e1;
    __syncthreads();
    for (int st = 128; st > 0; st >>= 1) {
        if (tid < st) red[tid] += red[tid + st];
        __syncthreads();
    }
    float inv = 1.0f / red[0];
    sc[tid]       = e0 * inv;
    sc[tid + 256] = e1 * inv;
    __syncthreads();

    if (kc == 0) {   // attn_weights output (region 3)
        wout[(size_t)tid * Bc + b]         = sc[tid];
        wout[(size_t)(tid + 256) * Bc + b] = sc[tid + 256];
    }

    // embedding copy for this k-chunk
    const int idx = input[b];
    const int k = kc * 256 + tid;
    g_x[(size_t)b * 2 * Hc + k] = emb[(size_t)idx * Hc + k];

    // context
    const float* p = enc + (size_t)b * Hc + k;
    float acc = 0.0f;
#pragma unroll 8
    for (int s = 0; s < Sc; s++)
        acc += sc[s] * p[(size_t)s * (Bc * Hc)];
    g_x[(size_t)b * 2 * Hc + Hc + k] = acc;
}

// GRU gate combine: sums the 4 split-K partials of gi/gh inline (exact fp32).
__global__ void __launch_bounds__(256)
gru_kernel(const float* __restrict__ hidden, float* __restrict__ hnew,
           const float* __restrict__ bih, const float* __restrict__ bhh)
{
    const int g = blockIdx.x * 256 + threadIdx.x;   // 65536
    const int b = g >> 10, h = g & 1023;

    float gir = bih[h],            ghr = bhh[h];
    float giz = bih[Hc + h],       ghz = bhh[Hc + h];
    float gin = bih[2 * Hc + h],   ghn = bhh[2 * Hc + h];
#pragma unroll
    for (int z = 0; z < 4; z++) {
        const float* gi = g_gip + (size_t)(z * 64 + b) * (3 * Hc);
        const float* gh = g_ghp + (size_t)(z * 64 + b) * (3 * Hc);
        gir += gi[h];          ghr += gh[h];
        giz += gi[Hc + h];     ghz += gh[Hc + h];
        gin += gi[2 * Hc + h]; ghn += gh[2 * Hc + h];
    }
    float r = 1.0f / (1.0f + expf(-(gir + ghr)));
    float z = 1.0f / (1.0f + expf(-(giz + ghz)));
    float n = tanhf(gin + r * ghn);
    float hp = hidden[g];
    hnew[g] = (1.0f - z) * n + z * hp;
}

// ===========================================================================
extern "C" void kernel_launch(void* const* d_in, const int* in_sizes, int n_in,
                              void* d_out, int out_size)
{
    const int*   input    = (const int*)d_in[0];
    const float* hidden   = (const float*)d_in[1];
    const float* enc      = (const float*)d_in[2];
    const float* emb      = (const float*)d_in[3];
    const float* attn_w_W = (const float*)d_in[4];
    const float* attn_w_b = (const float*)d_in[5];
    const float* attn_v_W = (const float*)d_in[6];
    // d_in[7] = attn_v_b : softmax-invariant, skipped
    const float* gru_Wih  = (const float*)d_in[8];
    const float* gru_Whh  = (const float*)d_in[9];
    const float* gru_bih  = (const float*)d_in[10];
    const float* gru_bhh  = (const float*)d_in[11];
    const float* out_W    = (const float*)d_in[12];
    const float* out_b    = (const float*)d_in[13];

    float* out    = (float*)d_out;
    float* logits = out;                        // B*V
    float* hnew   = out + (size_t)Bc * Vc;      // B*H
    float* wts    = hnew + (size_t)Bc * Hc;     // S*B

    float *p_hWhp, *p_gx, *p_gip, *p_ghp;
    cudaGetSymbolAddress((void**)&p_hWhp, g_hWhp);
    cudaGetSymbolAddress((void**)&p_gx,   g_x);
    cudaGetSymbolAddress((void**)&p_gip,  g_gip);
    cudaGetSymbolAddress((void**)&p_ghp,  g_ghp);

    cudaFuncSetAttribute(attn_score_tc, cudaFuncAttributeMaxDynamicSharedMemorySize, ATT_SMEM);

    // 1. combined: hWh partials + gh partials (exact fp32 split-K)
    splitk_pre<<<dim3(64, 1, 4), 256>>>(attn_w_W, hidden, gru_Whh, p_hWhp, p_ghp);
    // 2. reduce + bias -> g_hWh
    hwh_reduce<<<256, 256>>>(attn_w_b);
    // 3. fused attention scores (tf32 tensor + tanh + v-dot)   [profiled slot]
    attn_score_tc<<<dim3(8, 256), 256, ATT_SMEM>>>(enc, attn_w_W, attn_v_W);
    // 4. fused softmax + attn_weights + embed + context
    ctx_fused<<<dim3(4, Bc), 256>>>(enc, input, emb, wts);
    // 5. gi split-K partials (exact fp32)
    splitk_gi<<<dim3(48, 1, 4), 256>>>(gru_Wih, p_gx, p_gip);
    // 6. GRU combine (sums partials) -> h_new (output region 2)
    gru_kernel<<<Bc * Hc / 256, 256>>>(hidden, hnew, gru_bih, gru_bhh);
    // 7. logits = h_new @ out_W^T + out_b (3-term split-tf32, output region 1)
    gemm_wact_tc<<<Vc / 128, 256>>>(out_W, Hc, Hc, hnew, logits, Vc, out_b);
}

// round 8
// speedup vs baseline: 1.1285x; 1.1285x over previous
#include <cuda_runtime.h>
#include <cstdint>
#include <cstddef>

#define Bc 64
#define Sc 512
#define Hc 1024
#define Vc 32000
#define SB (Sc * Bc)

// ---------------- scratch (device globals, no allocation) ----------------
__device__ float g_hWh[Bc * Hc];         // reduced: [b][h] hidden@W_h^T + attn_w_b
__device__ float g_hWhp[4 * Bc * Hc];    // split-K partials
__device__ float g_spart[SB * 32];       // 32 partial scores per row r = s*B+b
__device__ float g_x[Bc * 2 * Hc];       // [b][emb ; context]
__device__ float g_gip[4 * Bc * 3 * Hc]; // gi split-K partials [z][b][3H]
__device__ float g_ghp[4 * Bc * 3 * Hc]; // gh split-K partials [z][b][3H]

// ---------------- portable-PTX helpers ----------------
__device__ __forceinline__ uint32_t smem_u32(const void* p) {
    uint32_t a;
    asm("{ .reg .u64 t; cvta.to.shared.u64 t, %1; cvt.u32.u64 %0, t; }"
        : "=r"(a) : "l"(p));
    return a;
}
#define CPA(dst, src) \
    asm volatile("cp.async.cg.shared.global [%0], [%1], 16;" :: "r"(dst), "l"(src))
#define CPCOMMIT() asm volatile("cp.async.commit_group;" ::: "memory")
#define CPWAIT(n)  asm volatile("cp.async.wait_group %0;" :: "n"(n) : "memory")

__device__ __forceinline__ void mma_tf32(float* c, const uint32_t* a, const uint32_t* b) {
    asm volatile(
        "mma.sync.aligned.m16n8k8.row.col.f32.tf32.tf32.f32 "
        "{%0,%1,%2,%3}, {%4,%5,%6,%7}, {%8,%9}, {%0,%1,%2,%3};"
        : "+f"(c[0]), "+f"(c[1]), "+f"(c[2]), "+f"(c[3])
        : "r"(a[0]), "r"(a[1]), "r"(a[2]), "r"(a[3]), "r"(b[0]), "r"(b[1]));
}
__device__ __forceinline__ void split_tf32(float x, uint32_t& hi, uint32_t& lo) {
    uint32_t h = __float_as_uint(x) & 0xFFFFE000u;
    hi = h;
    lo = __float_as_uint(x - __uint_as_float(h));   // exact (same exponent)
}

// ===========================================================================
// Attention score kernel (mma.sync tf32). CTA tile 128x128, warp tile 64x32.
// 3-stage pipeline, K=32 per stage, buffers STATIC via manual unroll-by-3,
// ONE sync per iteration (top-of-iter sync protects buffer (ks+2)%3, which
// was last read in iteration ks-1). 2 CTAs/SM.
// ===========================================================================
// smem: 3 stages x (A 128x36 + B 128x36 floats) = 110592 B
#define ATT_SMEM 110592

__global__ void __launch_bounds__(256, 2)
attn_score_tc(const float* __restrict__ enc, const float* __restrict__ W,
              const float* __restrict__ vvec)
{
    extern __shared__ float sm[];
    const int tid = threadIdx.x, lane = tid & 31, wid = tid >> 5;
    const int n0 = blockIdx.x * 128, m0 = blockIdx.y * 128;
    const int wm = (wid >> 2) * 64, wn = (wid & 3) * 32;
    const float* Wp = W + Hc;
    const uint32_t sbase = smem_u32(sm);
    const int fr = lane >> 2, fc = lane & 3;

    float acc[4][4][4] = {};

#define LOAD_STAGE(buf, kk)                                                   \
    do {                                                                      \
        const uint32_t db = sbase + (buf) * 36864u;                           \
        _Pragma("unroll")                                                     \
        for (int i_ = 0; i_ < 4; i_++) {                                      \
            int c_ = i_ * 256 + tid;                                          \
            int row_ = c_ >> 3, kc_ = c_ & 7;                                 \
            CPA(db + (row_ * 36 + kc_ * 4) * 4,                               \
                enc + (size_t)(m0 + row_) * Hc + (kk) + kc_ * 4);             \
            CPA(db + 18432u + (row_ * 36 + kc_ * 4) * 4,                      \
                Wp + (size_t)(n0 + row_) * (2 * Hc) + (kk) + kc_ * 4);        \
        }                                                                     \
        CPCOMMIT();                                                           \
    } while (0)

// One pipeline step: wait for stage ks, sync, issue load for ks+2, compute.
#define STEP(ks, buf)                                                         \
    do {                                                                      \
        CPWAIT(1);                                                            \
        __syncthreads();                                                      \
        if ((ks) + 2 < 32) LOAD_STAGE(((ks) + 2) % 3, ((ks) + 2) * 32);       \
        else               CPCOMMIT();                                        \
        const float* Sa = sm + (buf) * 9216;                                  \
        const float* Sb = Sa + 4608;                                          \
        _Pragma("unroll")                                                     \
        for (int kh = 0; kh < 4; kh++) {                                      \
            const int k8 = kh * 8;                                            \
            uint32_t a[4][4], b[4][2];                                        \
            _Pragma("unroll")                                                 \
            for (int mi = 0; mi < 4; mi++) {                                  \
                const float* ap = Sa + (wm + 16 * mi + fr) * 36 + k8 + fc;    \
                a[mi][0] = __float_as_uint(ap[0]);                            \
                a[mi][1] = __float_as_uint(ap[288]);                          \
                a[mi][2] = __float_as_uint(ap[4]);                            \
                a[mi][3] = __float_as_uint(ap[292]);                          \
            }                                                                 \
            _Pragma("unroll")                                                 \
            for (int nj = 0; nj < 4; nj++) {                                  \
                const float* bp = Sb + (wn + 8 * nj + fr) * 36 + k8 + fc;     \
                b[nj][0] = __float_as_uint(bp[0]);                            \
                b[nj][1] = __float_as_uint(bp[4]);                            \
            }                                                                 \
            _Pragma("unroll")                                                 \
            for (int mi = 0; mi < 4; mi++)                                    \
                _Pragma("unroll")                                             \
                for (int nj = 0; nj < 4; nj++)                                \
                    mma_tf32(acc[mi][nj], a[mi], b[nj]);                      \
        }                                                                     \
    } while (0)

    LOAD_STAGE(0, 0);
    LOAD_STAGE(1, 32);

    for (int ks = 0; ks < 30; ks += 3) {
        STEP(ks + 0, 0);
        STEP(ks + 1, 1);
        STEP(ks + 2, 2);
    }
    STEP(30, 0);
    STEP(31, 1);
#undef STEP
#undef LOAD_STAGE
    __syncthreads();   // all warps done with all stages before smem overlay

    // ---- epilogue: stage hWh slice (stride 133, conflict-free) + v slice ----
    float* shf = sm;
    float* shv = sm + 64 * 133;
    for (int j = tid; j < 64 * 128; j += 256) {
        int b = j >> 7, c = j & 127;
        shf[b * 133 + c] = g_hWh[b * Hc + n0 + c];
    }
    if (tid < 128) shv[tid] = vvec[n0 + tid];
    __syncthreads();

    const int c2 = (lane & 3) * 2;
    float s[4][2] = {};
#pragma unroll
    for (int mi = 0; mi < 4; mi++) {
        const int R0 = wm + 16 * mi + fr;
        const int b0 = R0 & 63, b1 = (R0 + 8) & 63;
#pragma unroll
        for (int nj = 0; nj < 4; nj++) {
            const int n = wn + 8 * nj + c2;
            const float v0 = shv[n], v1 = shv[n + 1];
            s[mi][0] += tanhf(acc[mi][nj][0] + shf[b0 * 133 + n]) * v0
                      + tanhf(acc[mi][nj][1] + shf[b0 * 133 + n + 1]) * v1;
            s[mi][1] += tanhf(acc[mi][nj][2] + shf[b1 * 133 + n]) * v0
                      + tanhf(acc[mi][nj][3] + shf[b1 * 133 + n + 1]) * v1;
        }
    }
#pragma unroll
    for (int mi = 0; mi < 4; mi++)
#pragma unroll
        for (int h = 0; h < 2; h++) {
            s[mi][h] += __shfl_xor_sync(0xffffffffu, s[mi][h], 1);
            s[mi][h] += __shfl_xor_sync(0xffffffffu, s[mi][h], 2);
        }
    if ((lane & 3) == 0) {
        const int col = blockIdx.x * 4 + (wid & 3);
#pragma unroll
        for (int mi = 0; mi < 4; mi++) {
            const int R0 = wm + 16 * mi + fr;
            g_spart[(size_t)(m0 + R0) * 32 + col]     = s[mi][0];
            g_spart[(size_t)(m0 + R0 + 8) * 32 + col] = s[mi][1];
        }
    }
}

// ===========================================================================
// Exact fp32 SIMT split-K GEMM body (device function).
// Cpart[z*64+n][m0+m] = A[m0+m, zKs:(z+1)Ks] . act[n, zKs:(z+1)Ks]
// ===========================================================================
__device__ __forceinline__ void splitk_body(
    const float* __restrict__ A, int lda,
    const float* __restrict__ act, int ldact,
    float* __restrict__ Cpart, int M, int Ks, int m0, int z)
{
    __shared__ float As[16][68];
    __shared__ float Bs[16][68];
    const int tid = threadIdx.x;

    const int lrow = tid >> 2, lk = (tid & 3) * 4;
    const float* Ap = A + (size_t)(m0 + lrow) * lda + z * Ks + lk;
    const float* Bp = act + (size_t)lrow * ldact + z * Ks + lk;

    const int ty = tid >> 4, tx = tid & 15;
    float acc[4][4] = {};

    for (int k0 = 0; k0 < Ks; k0 += 16) {
        float4 av = *(const float4*)(Ap + k0);
        float4 bv = *(const float4*)(Bp + k0);
        As[lk + 0][lrow] = av.x; As[lk + 1][lrow] = av.y;
        As[lk + 2][lrow] = av.z; As[lk + 3][lrow] = av.w;
        Bs[lk + 0][lrow] = bv.x; Bs[lk + 1][lrow] = bv.y;
        Bs[lk + 2][lrow] = bv.z; Bs[lk + 3][lrow] = bv.w;
        __syncthreads();
#pragma unroll
        for (int k = 0; k < 16; k++) {
            float4 a = *(const float4*)&As[k][ty * 4];
            float4 b = *(const float4*)&Bs[k][tx * 4];
            float ar[4] = {a.x, a.y, a.z, a.w};
            float br[4] = {b.x, b.y, b.z, b.w};
#pragma unroll
            for (int i = 0; i < 4; i++)
#pragma unroll
                for (int j = 0; j < 4; j++)
                    acc[i][j] += ar[i] * br[j];
        }
        __syncthreads();
    }

#pragma unroll
    for (int i = 0; i < 4; i++)
#pragma unroll
        for (int j = 0; j < 4; j++)
            Cpart[(size_t)(z * 64 + tx * 4 + j) * M + m0 + ty * 4 + i] = acc[i][j];
}

// Combined pre-attention split-K launch: hWh partials (bx<16) + gh partials.
__global__ void __launch_bounds__(256)
splitk_pre(const float* __restrict__ attn_w_W, const float* __restrict__ hidden,
           const float* __restrict__ gru_Whh,
           float* __restrict__ hWhp, float* __restrict__ ghp)
{
    const int bx = blockIdx.x, z = blockIdx.z;
    if (bx < 16)
        splitk_body(attn_w_W, 2 * Hc, hidden, Hc, hWhp, Hc, 256, bx * 64, z);
    else
        splitk_body(gru_Whh, Hc, hidden, Hc, ghp, 3 * Hc, 256, (bx - 16) * 64, z);
}

// gi partials (post-context)
__global__ void __launch_bounds__(256)
splitk_gi(const float* __restrict__ gru_Wih, const float* __restrict__ x,
          float* __restrict__ gip)
{
    splitk_body(gru_Wih, 2 * Hc, x, 2 * Hc, gip, 3 * Hc, 512, blockIdx.x * 64, blockIdx.z);
}

// Reduce hWh partials + attn_w_b -> g_hWh
__global__ void __launch_bounds__(256)
hwh_reduce(const float* __restrict__ awb)
{
    const int idx = blockIdx.x * 256 + threadIdx.x;   // 65536
    const int b = idx >> 10, h = idx & 1023;
    float v = awb[h];
#pragma unroll
    for (int z = 0; z < 4; z++) v += g_hWhp[(size_t)(z * 64 + b) * Hc + h];
    g_hWh[idx] = v;
}

// ===========================================================================
// Logits GEMM: 3-term split-tf32 (near-fp32 accuracy on tensor cores).
// ===========================================================================
__global__ void __launch_bounds__(256)
gemm_wact_tc(const float* __restrict__ A, int lda, int K,
             const float* __restrict__ act,
             float* __restrict__ C, int ldc,
             const float* __restrict__ bias)
{
    __shared__ float sm[7680];   // [2 bufs][ A:128x20 | act:64x20 ]
    const int tid = threadIdx.x, lane = tid & 31, wid = tid >> 5;
    const int m0 = blockIdx.x * 128;
    const int wm = (wid & 3) * 32, wn = (wid >> 2) * 32;

    float acc[2][4][4] = {};

    const int lr = tid >> 2, lc = (tid & 3) * 4;
    const float* Ag0 = A + (size_t)(m0 + lr) * lda + lc;
    const float* Ag1 = A + (size_t)(m0 + lr + 64) * lda + lc;
    const float* Cg  = act + (size_t)lr * K + lc;
    const uint32_t sA0 = smem_u32(&sm[lr * 20 + lc]);
    const uint32_t sA1 = smem_u32(&sm[(lr + 64) * 20 + lc]);
    const uint32_t sC0 = smem_u32(&sm[2560 + lr * 20 + lc]);

#define W_LOAD(buf, k0)                                     \
    do {                                                    \
        CPA(sA0 + (buf) * 15360, Ag0 + (k0));               \
        CPA(sA1 + (buf) * 15360, Ag1 + (k0));               \
        CPA(sC0 + (buf) * 15360, Cg + (k0));                \
        CPCOMMIT();                                         \
    } while (0)

    const int NS = K / 16;
    W_LOAD(0, 0);
    const int fr = lane >> 2, fc = lane & 3;

    for (int ks = 0; ks < NS; ks++) {
        const int buf = ks & 1;
        if (ks + 1 < NS) { W_LOAD(buf ^ 1, (ks + 1) * 16); CPWAIT(1); }
        else             { CPWAIT(0); }
        __syncthreads();
        const float* As = &sm[buf * 3840];
        const float* Bs = &sm[buf * 3840 + 2560];
#pragma unroll
        for (int kh = 0; kh < 2; kh++) {
            const int k8 = kh * 8;
            uint32_t ah[2][4], al[2][4], bh[4][2], bl[4][2];
#pragma unroll
            for (int mi = 0; mi < 2; mi++) {
                const float* ap = As + (wm + 16 * mi + fr) * 20 + k8 + fc;
                split_tf32(ap[0],   ah[mi][0], al[mi][0]);
                split_tf32(ap[160], ah[mi][1], al[mi][1]);
                split_tf32(ap[4],   ah[mi][2], al[mi][2]);
                split_tf32(ap[164], ah[mi][3], al[mi][3]);
            }
#pragma unroll
            for (int nj = 0; nj < 4; nj++) {
                const float* bp = Bs + (wn + 8 * nj + fr) * 20 + k8 + fc;
                split_tf32(bp[0], bh[nj][0], bl[nj][0]);
                split_tf32(bp[4], bh[nj][1], bl[nj][1]);
            }
#pragma unroll
            for (int mi = 0; mi < 2; mi++)
#pragma unroll
                for (int nj = 0; nj < 4; nj++) {
                    mma_tf32(acc[mi][nj], ah[mi], bl[nj]);
                    mma_tf32(acc[mi][nj], al[mi], bh[nj]);
                    mma_tf32(acc[mi][nj], ah[mi], bh[nj]);
                }
        }
        __syncthreads();
    }
#undef W_LOAD

    const int c2 = (lane & 3) * 2;
#pragma unroll
    for (int mi = 0; mi < 2; mi++) {
        const int m = m0 + wm + 16 * mi + fr;
        const float bm0 = bias[m], bm1 = bias[m + 8];
#pragma unroll
        for (int nj = 0; nj < 4; nj++) {
            const int n = wn + 8 * nj + c2;
            C[(size_t)n * ldc + m]           = acc[mi][nj][0] + bm0;
            C[(size_t)(n + 1) * ldc + m]     = acc[mi][nj][1] + bm0;
            C[(size_t)n * ldc + m + 8]       = acc[mi][nj][2] + bm1;
            C[(size_t)(n + 1) * ldc + m + 8] = acc[mi][nj][3] + bm1;
        }
    }
}

// ===========================================================================
// Fused: per-b softmax (local recompute) + attn_weights write (kc==0) +
// embedding copy + context. grid (4 k-chunks, 64 b). Deep unroll for MLP.
// ===========================================================================
__global__ void __launch_bounds__(256)
ctx_fused(const float* __restrict__ enc, const int* __restrict__ input,
          const float* __restrict__ emb, float* __restrict__ wout)
{
    __shared__ float sc[Sc];
    __shared__ float red[256];
    const int kc = blockIdx.x, b = blockIdx.y, tid = threadIdx.x;

    for (int s = tid; s < Sc; s += 256) {
        const float4* p = (const float4*)&g_spart[(size_t)(s * Bc + b) * 32];
        float v = 0.0f;
#pragma unroll
        for (int i = 0; i < 8; i++) {
            float4 q = p[i];
            v += q.x + q.y + q.z + q.w;
        }
        sc[s] = v;
    }
    __syncthreads();

    float m = fmaxf(sc[tid], sc[tid + 256]);
    red[tid] = m;
    __syncthreads();
    for (int st = 128; st > 0; st >>= 1) {
        if (tid < st) red[tid] = fmaxf(red[tid], red[tid + st]);
        __syncthreads();
    }
    float mx = red[0];
    __syncthreads();

    float e0 = expf(sc[tid] - mx);
    float e1 = expf(sc[tid + 256] - mx);
    red[tid] = e0 + e1;
    __syncthreads();
    for (int st = 128; st > 0; st >>= 1) {
        if (tid < st) red[tid] += red[tid + st];
        __syncthreads();
    }
    float inv = 1.0f / red[0];
    sc[tid]       = e0 * inv;
    sc[tid + 256] = e1 * inv;
    __syncthreads();

    if (kc == 0) {   // attn_weights output (region 3)
        wout[(size_t)tid * Bc + b]         = sc[tid];
        wout[(size_t)(tid + 256) * Bc + b] = sc[tid + 256];
    }

    // embedding copy for this k-chunk
    const int idx = input[b];
    const int k = kc * 256 + tid;
    g_x[(size_t)b * 2 * Hc + k] = emb[(size_t)idx * Hc + k];

    // context (deep unroll -> 16 outstanding loads)
    const float* p = enc + (size_t)b * Hc + k;
    float acc = 0.0f;
#pragma unroll 16
    for (int s = 0; s < Sc; s++)
        acc += sc[s] * p[(size_t)s * (Bc * Hc)];
    g_x[(size_t)b * 2 * Hc + Hc + k] = acc;
}

// GRU gate combine: sums the 4 split-K partials of gi/gh inline (exact fp32).
__global__ void __launch_bounds__(256)
gru_kernel(const float* __restrict__ hidden, float* __restrict__ hnew,
           const float* __restrict__ bih, const float* __restrict__ bhh)
{
    const int g = blockIdx.x * 256 + threadIdx.x;   // 65536
    const int b = g >> 10, h = g & 1023;

    float gir = bih[h],            ghr = bhh[h];
    float giz = bih[Hc + h],       ghz = bhh[Hc + h];
    float gin = bih[2 * Hc + h],   ghn = bhh[2 * Hc + h];
#pragma unroll
    for (int z = 0; z < 4; z++) {
        const float* gi = g_gip + (size_t)(z * 64 + b) * (3 * Hc);
        const float* gh = g_ghp + (size_t)(z * 64 + b) * (3 * Hc);
        gir += gi[h];          ghr += gh[h];
        giz += gi[Hc + h];     ghz += gh[Hc + h];
        gin += gi[2 * Hc + h]; ghn += gh[2 * Hc + h];
    }
    float r = 1.0f / (1.0f + expf(-(gir + ghr)));
    float z = 1.0f / (1.0f + expf(-(giz + ghz)));
    float n = tanhf(gin + r * ghn);
    float hp = hidden[g];
    hnew[g] = (1.0f - z) * n + z * hp;
}

// ===========================================================================
extern "C" void kernel_launch(void* const* d_in, const int* in_sizes, int n_in,
                              void* d_out, int out_size)
{
    const int*   input    = (const int*)d_in[0];
    const float* hidden   = (const float*)d_in[1];
    const float* enc      = (const float*)d_in[2];
    const float* emb      = (const float*)d_in[3];
    const float* attn_w_W = (const float*)d_in[4];
    const float* attn_w_b = (const float*)d_in[5];
    const float* attn_v_W = (const float*)d_in[6];
    // d_in[7] = attn_v_b : softmax-invariant, skipped
    const float* gru_Wih  = (const float*)d_in[8];
    const float* gru_Whh  = (const float*)d_in[9];
    const float* gru_bih  = (const float*)d_in[10];
    const float* gru_bhh  = (const float*)d_in[11];
    const float* out_W    = (const float*)d_in[12];
    const float* out_b    = (const float*)d_in[13];

    float* out    = (float*)d_out;
    float* logits = out;                        // B*V
    float* hnew   = out + (size_t)Bc * Vc;      // B*H
    float* wts    = hnew + (size_t)Bc * Hc;     // S*B

    float *p_hWhp, *p_gx, *p_gip, *p_ghp;
    cudaGetSymbolAddress((void**)&p_hWhp, g_hWhp);
    cudaGetSymbolAddress((void**)&p_gx,   g_x);
    cudaGetSymbolAddress((void**)&p_gip,  g_gip);
    cudaGetSymbolAddress((void**)&p_ghp,  g_ghp);

    cudaFuncSetAttribute(attn_score_tc, cudaFuncAttributeMaxDynamicSharedMemorySize, ATT_SMEM);

    // 1. combined: hWh partials + gh partials (exact fp32 split-K)
    splitk_pre<<<dim3(64, 1, 4), 256>>>(attn_w_W, hidden, gru_Whh, p_hWhp, p_ghp);
    // 2. reduce + bias -> g_hWh
    hwh_reduce<<<256, 256>>>(attn_w_b);
    // 3. fused attention scores (tf32 tensor + tanh + v-dot)   [profiled slot]
    attn_score_tc<<<dim3(8, 256), 256, ATT_SMEM>>>(enc, attn_w_W, attn_v_W);
    // 4. fused softmax + attn_weights + embed + context
    ctx_fused<<<dim3(4, Bc), 256>>>(enc, input, emb, wts);
    // 5. gi split-K partials (exact fp32)
    splitk_gi<<<dim3(48, 1, 4), 256>>>(gru_Wih, p_gx, p_gip);
    // 6. GRU combine (sums partials) -> h_new (output region 2)
    gru_kernel<<<Bc * Hc / 256, 256>>>(hidden, hnew, gru_bih, gru_bhh);
    // 7. logits = h_new @ out_W^T + out_b (3-term split-tf32, output region 1)
    gemm_wact_tc<<<Vc / 128, 256>>>(out_W, Hc, Hc, hnew, logits, Vc, out_b);
}

// round 9
// speedup vs baseline: 1.1630x; 1.0306x over previous
#include <cuda_runtime.h>
#include <cstdint>
#include <cstddef>

#define Bc 64
#define Sc 512
#define Hc 1024
#define Vc 32000
#define SB (Sc * Bc)

// ---------------- scratch (device globals, no allocation) ----------------
__device__ float g_hWh[Bc * Hc];         // reduced: [b][h] hidden@W_h^T + attn_w_b
__device__ float g_hWhp[4 * Bc * Hc];    // split-K partials
__device__ float g_spart[SB * 32];       // 32 partial scores per row r = s*B+b
__device__ float g_x[Bc * 2 * Hc];       // [b][emb ; context]
__device__ float g_gip[4 * Bc * 3 * Hc]; // gi split-K partials [z][b][3H]
__device__ float g_ghp[4 * Bc * 3 * Hc]; // gh split-K partials [z][b][3H]

// ---------------- portable-PTX helpers ----------------
__device__ __forceinline__ uint32_t smem_u32(const void* p) {
    uint32_t a;
    asm("{ .reg .u64 t; cvta.to.shared.u64 t, %1; cvt.u32.u64 %0, t; }"
        : "=r"(a) : "l"(p));
    return a;
}
#define CPA(dst, src) \
    asm volatile("cp.async.cg.shared.global [%0], [%1], 16;" :: "r"(dst), "l"(src))
#define CPCOMMIT() asm volatile("cp.async.commit_group;" ::: "memory")
#define CPWAIT(n)  asm volatile("cp.async.wait_group %0;" :: "n"(n) : "memory")

__device__ __forceinline__ void mma_tf32(float* c, const uint32_t* a, const uint32_t* b) {
    asm volatile(
        "mma.sync.aligned.m16n8k8.row.col.f32.tf32.tf32.f32 "
        "{%0,%1,%2,%3}, {%4,%5,%6,%7}, {%8,%9}, {%0,%1,%2,%3};"
        : "+f"(c[0]), "+f"(c[1]), "+f"(c[2]), "+f"(c[3])
        : "r"(a[0]), "r"(a[1]), "r"(a[2]), "r"(a[3]), "r"(b[0]), "r"(b[1]));
}
__device__ __forceinline__ void split_tf32(float x, uint32_t& hi, uint32_t& lo) {
    uint32_t h = __float_as_uint(x) & 0xFFFFE000u;
    hi = h;
    lo = __float_as_uint(x - __uint_as_float(h));   // exact (same exponent)
}

// ===========================================================================
// Attention score kernel (mma.sync tf32). CTA tile 128x128, warp tile 64x32.
// 3-stage pipeline, K=32 per stage, buffers STATIC via manual unroll-by-3,
// ONE sync per iteration. 2 CTAs/SM.   [R8 proven — unchanged]
// ===========================================================================
#define ATT_SMEM 110592

__global__ void __launch_bounds__(256, 2)
attn_score_tc(const float* __restrict__ enc, const float* __restrict__ W,
              const float* __restrict__ vvec)
{
    extern __shared__ float sm[];
    const int tid = threadIdx.x, lane = tid & 31, wid = tid >> 5;
    const int n0 = blockIdx.x * 128, m0 = blockIdx.y * 128;
    const int wm = (wid >> 2) * 64, wn = (wid & 3) * 32;
    const float* Wp = W + Hc;
    const uint32_t sbase = smem_u32(sm);
    const int fr = lane >> 2, fc = lane & 3;

    float acc[4][4][4] = {};

#define LOAD_STAGE(buf, kk)                                                   \
    do {                                                                      \
        const uint32_t db = sbase + (buf) * 36864u;                           \
        _Pragma("unroll")                                                     \
        for (int i_ = 0; i_ < 4; i_++) {                                      \
            int c_ = i_ * 256 + tid;                                          \
            int row_ = c_ >> 3, kc_ = c_ & 7;                                 \
            CPA(db + (row_ * 36 + kc_ * 4) * 4,                               \
                enc + (size_t)(m0 + row_) * Hc + (kk) + kc_ * 4);             \
            CPA(db + 18432u + (row_ * 36 + kc_ * 4) * 4,                      \
                Wp + (size_t)(n0 + row_) * (2 * Hc) + (kk) + kc_ * 4);        \
        }                                                                     \
        CPCOMMIT();                                                           \
    } while (0)

#define STEP(ks, buf)                                                         \
    do {                                                                      \
        CPWAIT(1);                                                            \
        __syncthreads();                                                      \
        if ((ks) + 2 < 32) LOAD_STAGE(((ks) + 2) % 3, ((ks) + 2) * 32);       \
        else               CPCOMMIT();                                        \
        const float* Sa = sm + (buf) * 9216;                                  \
        const float* Sb = Sa + 4608;                                          \
        _Pragma("unroll")                                                     \
        for (int kh = 0; kh < 4; kh++) {                                      \
            const int k8 = kh * 8;                                            \
            uint32_t a[4][4], b[4][2];                                        \
            _Pragma("unroll")                                                 \
            for (int mi = 0; mi < 4; mi++) {                                  \
                const float* ap = Sa + (wm + 16 * mi + fr) * 36 + k8 + fc;    \
                a[mi][0] = __float_as_uint(ap[0]);                            \
                a[mi][1] = __float_as_uint(ap[288]);                          \
                a[mi][2] = __float_as_uint(ap[4]);                            \
                a[mi][3] = __float_as_uint(ap[292]);                          \
            }                                                                 \
            _Pragma("unroll")                                                 \
            for (int nj = 0; nj < 4; nj++) {                                  \
                const float* bp = Sb + (wn + 8 * nj + fr) * 36 + k8 + fc;     \
                b[nj][0] = __float_as_uint(bp[0]);                            \
                b[nj][1] = __float_as_uint(bp[4]);                            \
            }                                                                 \
            _Pragma("unroll")                                                 \
            for (int mi = 0; mi < 4; mi++)                                    \
                _Pragma("unroll")                                             \
                for (int nj = 0; nj < 4; nj++)                                \
                    mma_tf32(acc[mi][nj], a[mi], b[nj]);                      \
        }                                                                     \
    } while (0)

    LOAD_STAGE(0, 0);
    LOAD_STAGE(1, 32);

    for (int ks = 0; ks < 30; ks += 3) {
        STEP(ks + 0, 0);
        STEP(ks + 1, 1);
        STEP(ks + 2, 2);
    }
    STEP(30, 0);
    STEP(31, 1);
#undef STEP
#undef LOAD_STAGE
    __syncthreads();

    // ---- epilogue: stage hWh slice (stride 133, conflict-free) + v slice ----
    float* shf = sm;
    float* shv = sm + 64 * 133;
    for (int j = tid; j < 64 * 128; j += 256) {
        int b = j >> 7, c = j & 127;
        shf[b * 133 + c] = g_hWh[b * Hc + n0 + c];
    }
    if (tid < 128) shv[tid] = vvec[n0 + tid];
    __syncthreads();

    const int c2 = (lane & 3) * 2;
    float s[4][2] = {};
#pragma unroll
    for (int mi = 0; mi < 4; mi++) {
        const int R0 = wm + 16 * mi + fr;
        const int b0 = R0 & 63, b1 = (R0 + 8) & 63;
#pragma unroll
        for (int nj = 0; nj < 4; nj++) {
            const int n = wn + 8 * nj + c2;
            const float v0 = shv[n], v1 = shv[n + 1];
            s[mi][0] += tanhf(acc[mi][nj][0] + shf[b0 * 133 + n]) * v0
                      + tanhf(acc[mi][nj][1] + shf[b0 * 133 + n + 1]) * v1;
            s[mi][1] += tanhf(acc[mi][nj][2] + shf[b1 * 133 + n]) * v0
                      + tanhf(acc[mi][nj][3] + shf[b1 * 133 + n + 1]) * v1;
        }
    }
#pragma unroll
    for (int mi = 0; mi < 4; mi++)
#pragma unroll
        for (int h = 0; h < 2; h++) {
            s[mi][h] += __shfl_xor_sync(0xffffffffu, s[mi][h], 1);
            s[mi][h] += __shfl_xor_sync(0xffffffffu, s[mi][h], 2);
        }
    if ((lane & 3) == 0) {
        const int col = blockIdx.x * 4 + (wid & 3);
#pragma unroll
        for (int mi = 0; mi < 4; mi++) {
            const int R0 = wm + 16 * mi + fr;
            g_spart[(size_t)(m0 + R0) * 32 + col]     = s[mi][0];
            g_spart[(size_t)(m0 + R0 + 8) * 32 + col] = s[mi][1];
        }
    }
}

// ===========================================================================
// Exact fp32 SIMT split-K GEMM body (device function).
// ===========================================================================
__device__ __forceinline__ void splitk_body(
    const float* __restrict__ A, int lda,
    const float* __restrict__ act, int ldact,
    float* __restrict__ Cpart, int M, int Ks, int m0, int z)
{
    __shared__ float As[16][68];
    __shared__ float Bs[16][68];
    const int tid = threadIdx.x;

    const int lrow = tid >> 2, lk = (tid & 3) * 4;
    const float* Ap = A + (size_t)(m0 + lrow) * lda + z * Ks + lk;
    const float* Bp = act + (size_t)lrow * ldact + z * Ks + lk;

    const int ty = tid >> 4, tx = tid & 15;
    float acc[4][4] = {};

    for (int k0 = 0; k0 < Ks; k0 += 16) {
        float4 av = *(const float4*)(Ap + k0);
        float4 bv = *(const float4*)(Bp + k0);
        As[lk + 0][lrow] = av.x; As[lk + 1][lrow] = av.y;
        As[lk + 2][lrow] = av.z; As[lk + 3][lrow] = av.w;
        Bs[lk + 0][lrow] = bv.x; Bs[lk + 1][lrow] = bv.y;
        Bs[lk + 2][lrow] = bv.z; Bs[lk + 3][lrow] = bv.w;
        __syncthreads();
#pragma unroll
        for (int k = 0; k < 16; k++) {
            float4 a = *(const float4*)&As[k][ty * 4];
            float4 b = *(const float4*)&Bs[k][tx * 4];
            float ar[4] = {a.x, a.y, a.z, a.w};
            float br[4] = {b.x, b.y, b.z, b.w};
#pragma unroll
            for (int i = 0; i < 4; i++)
#pragma unroll
                for (int j = 0; j < 4; j++)
                    acc[i][j] += ar[i] * br[j];
        }
        __syncthreads();
    }

#pragma unroll
    for (int i = 0; i < 4; i++)
#pragma unroll
        for (int j = 0; j < 4; j++)
            Cpart[(size_t)(z * 64 + tx * 4 + j) * M + m0 + ty * 4 + i] = acc[i][j];
}

// Combined pre-attention split-K launch: hWh partials (bx<16) + gh partials.
__global__ void __launch_bounds__(256)
splitk_pre(const float* __restrict__ attn_w_W, const float* __restrict__ hidden,
           const float* __restrict__ gru_Whh,
           float* __restrict__ hWhp, float* __restrict__ ghp)
{
    const int bx = blockIdx.x, z = blockIdx.z;
    if (bx < 16)
        splitk_body(attn_w_W, 2 * Hc, hidden, Hc, hWhp, Hc, 256, bx * 64, z);
    else
        splitk_body(gru_Whh, Hc, hidden, Hc, ghp, 3 * Hc, 256, (bx - 16) * 64, z);
}

// gi partials (post-context)
__global__ void __launch_bounds__(256)
splitk_gi(const float* __restrict__ gru_Wih, const float* __restrict__ x,
          float* __restrict__ gip)
{
    splitk_body(gru_Wih, 2 * Hc, x, 2 * Hc, gip, 3 * Hc, 512, blockIdx.x * 64, blockIdx.z);
}

// Reduce hWh partials + attn_w_b -> g_hWh
__global__ void __launch_bounds__(256)
hwh_reduce(const float* __restrict__ awb)
{
    const int idx = blockIdx.x * 256 + threadIdx.x;   // 65536
    const int b = idx >> 10, h = idx & 1023;
    float v = awb[h];
#pragma unroll
    for (int z = 0; z < 4; z++) v += g_hWhp[(size_t)(z * 64 + b) * Hc + h];
    g_hWh[idx] = v;
}

// ===========================================================================
// Logits GEMM: 3-term split-tf32, now with the R8-proven 3-stage K=32
// static-unroll-3 one-sync pipeline.
// ===========================================================================
// smem: 3 stages x (A 128x36 + act 64x36 floats) = 82944 B
#define LG_SMEM 82944

__global__ void __launch_bounds__(256, 2)
gemm_wact_tc(const float* __restrict__ A, int lda,
             const float* __restrict__ act,
             float* __restrict__ C, int ldc,
             const float* __restrict__ bias)
{
    extern __shared__ float sm[];
    const int tid = threadIdx.x, lane = tid & 31, wid = tid >> 5;
    const int m0 = blockIdx.x * 128;
    const int wm = (wid & 3) * 32, wn = (wid >> 2) * 32;
    const uint32_t sbase = smem_u32(sm);
    const int fr = lane >> 2, fc = lane & 3;

    float acc[2][4][4] = {};

#define LG_LOAD(buf, kk)                                                      \
    do {                                                                      \
        const uint32_t db = sbase + (buf) * 27648u;                           \
        _Pragma("unroll")                                                     \
        for (int i_ = 0; i_ < 4; i_++) {                                      \
            int c_ = i_ * 256 + tid;                                          \
            int row_ = c_ >> 3, kc_ = c_ & 7;                                 \
            CPA(db + (row_ * 36 + kc_ * 4) * 4,                               \
                A + (size_t)(m0 + row_) * lda + (kk) + kc_ * 4);              \
        }                                                                     \
        _Pragma("unroll")                                                     \
        for (int i_ = 0; i_ < 2; i_++) {                                      \
            int c_ = i_ * 256 + tid;                                          \
            int row_ = c_ >> 3, kc_ = c_ & 7;                                 \
            CPA(db + 18432u + (row_ * 36 + kc_ * 4) * 4,                      \
                act + (size_t)row_ * Hc + (kk) + kc_ * 4);                    \
        }                                                                     \
        CPCOMMIT();                                                           \
    } while (0)

#define LG_STEP(ks, buf)                                                      \
    do {                                                                      \
        CPWAIT(1);                                                            \
        __syncthreads();                                                      \
        if ((ks) + 2 < 32) LG_LOAD(((ks) + 2) % 3, ((ks) + 2) * 32);          \
        else               CPCOMMIT();                                        \
        const float* Sa = sm + (buf) * 6912;                                  \
        const float* Sb = Sa + 4608;                                          \
        _Pragma("unroll")                                                     \
        for (int kh = 0; kh < 4; kh++) {                                      \
            const int k8 = kh * 8;                                            \
            uint32_t ah[2][4], al[2][4], bh[4][2], bl[4][2];                  \
            _Pragma("unroll")                                                 \
            for (int mi = 0; mi < 2; mi++) {                                  \
                const float* ap = Sa + (wm + 16 * mi + fr) * 36 + k8 + fc;    \
                split_tf32(ap[0],   ah[mi][0], al[mi][0]);                    \
                split_tf32(ap[288], ah[mi][1], al[mi][1]);                    \
                split_tf32(ap[4],   ah[mi][2], al[mi][2]);                    \
                split_tf32(ap[292], ah[mi][3], al[mi][3]);                    \
            }                                                                 \
            _Pragma("unroll")                                                 \
            for (int nj = 0; nj < 4; nj++) {                                  \
                const float* bp = Sb + (wn + 8 * nj + fr) * 36 + k8 + fc;     \
                split_tf32(bp[0], bh[nj][0], bl[nj][0]);                      \
                split_tf32(bp[4], bh[nj][1], bl[nj][1]);                      \
            }                                                                 \
            _Pragma("unroll")                                                 \
            for (int mi = 0; mi < 2; mi++)                                    \
                _Pragma("unroll")                                             \
                for (int nj = 0; nj < 4; nj++) {                              \
                    mma_tf32(acc[mi][nj], ah[mi], bl[nj]);                    \
                    mma_tf32(acc[mi][nj], al[mi], bh[nj]);                    \
                    mma_tf32(acc[mi][nj], ah[mi], bh[nj]);                    \
                }                                                             \
        }                                                                     \
    } while (0)

    LG_LOAD(0, 0);
    LG_LOAD(1, 32);

    for (int ks = 0; ks < 30; ks += 3) {
        LG_STEP(ks + 0, 0);
        LG_STEP(ks + 1, 1);
        LG_STEP(ks + 2, 2);
    }
    LG_STEP(30, 0);
    LG_STEP(31, 1);
#undef LG_STEP
#undef LG_LOAD

    const int c2 = (lane & 3) * 2;
#pragma unroll
    for (int mi = 0; mi < 2; mi++) {
        const int m = m0 + wm + 16 * mi + fr;
        const float bm0 = bias[m], bm1 = bias[m + 8];
#pragma unroll
        for (int nj = 0; nj < 4; nj++) {
            const int n = wn + 8 * nj + c2;
            C[(size_t)n * ldc + m]           = acc[mi][nj][0] + bm0;
            C[(size_t)(n + 1) * ldc + m]     = acc[mi][nj][1] + bm0;
            C[(size_t)n * ldc + m + 8]       = acc[mi][nj][2] + bm1;
            C[(size_t)(n + 1) * ldc + m + 8] = acc[mi][nj][3] + bm1;
        }
    }
}

// ===========================================================================
// Softmax over seq (512) per batch; writes attn_weights (output region 3).
// ===========================================================================
__global__ void __launch_bounds__(256)
softmax_kernel(float* __restrict__ wout)
{
    __shared__ float sc[Sc];
    __shared__ float red[256];
    const int b = blockIdx.x, tid = threadIdx.x;

    for (int s = tid; s < Sc; s += 256) {
        const float4* p = (const float4*)&g_spart[(size_t)(s * Bc + b) * 32];
        float v = 0.0f;
#pragma unroll
        for (int i = 0; i < 8; i++) {
            float4 q = p[i];
            v += q.x + q.y + q.z + q.w;
        }
        sc[s] = v;
    }
    __syncthreads();

    float m = fmaxf(sc[tid], sc[tid + 256]);
    red[tid] = m;
    __syncthreads();
    for (int st = 128; st > 0; st >>= 1) {
        if (tid < st) red[tid] = fmaxf(red[tid], red[tid + st]);
        __syncthreads();
    }
    float mx = red[0];
    __syncthreads();

    float e0 = expf(sc[tid] - mx);
    float e1 = expf(sc[tid + 256] - mx);
    red[tid] = e0 + e1;
    __syncthreads();
    for (int st = 128; st > 0; st >>= 1) {
        if (tid < st) red[tid] += red[tid + st];
        __syncthreads();
    }
    float inv = 1.0f / red[0];

    wout[(size_t)tid * Bc + b]         = e0 * inv;
    wout[(size_t)(tid + 256) * Bc + b] = e1 * inv;
}

// ===========================================================================
// Context + embedding. grid (16 k-chunks, 64 b), 256 threads.
// Thread t: k = kc*64 + (t&63); s-range = (t>>6)*128..+128; smem combine.
// ===========================================================================
__global__ void __launch_bounds__(256)
ctx_kernel(const float* __restrict__ enc, const int* __restrict__ input,
           const float* __restrict__ emb, const float* __restrict__ wts)
{
    __shared__ float w[Sc];
    __shared__ float part[4][64];
    const int kc = blockIdx.x, b = blockIdx.y, tid = threadIdx.x;

    w[tid]       = wts[(size_t)tid * Bc + b];
    w[tid + 256] = wts[(size_t)(tid + 256) * Bc + b];

    const int kk = tid & 63, sg = tid >> 6;
    const int k = kc * 64 + kk;

    if (sg == 3) {   // embedding copy for this CTA's 64-k slice
        const int idx = input[b];
        g_x[(size_t)b * 2 * Hc + k] = emb[(size_t)idx * Hc + k];
    }
    __syncthreads();

    const float* p = enc + ((size_t)(sg * 128) * Bc + b) * Hc + k;
    const float* wp = w + sg * 128;
    float acc = 0.0f;
#pragma unroll 8
    for (int s = 0; s < 128; s++)
        acc += wp[s] * p[(size_t)s * (Bc * Hc)];
    part[sg][kk] = acc;
    __syncthreads();

    if (tid < 64)
        g_x[(size_t)b * 2 * Hc + Hc + kc * 64 + tid] =
            (part[0][tid] + part[1][tid]) + (part[2][tid] + part[3][tid]);
}

// GRU gate combine: sums the 4 split-K partials of gi/gh inline (exact fp32).
__global__ void __launch_bounds__(256)
gru_kernel(const float* __restrict__ hidden, float* __restrict__ hnew,
           const float* __restrict__ bih, const float* __restrict__ bhh)
{
    const int g = blockIdx.x * 256 + threadIdx.x;   // 65536
    const int b = g >> 10, h = g & 1023;

    float gir = bih[h],            ghr = bhh[h];
    float giz = bih[Hc + h],       ghz = bhh[Hc + h];
    float gin = bih[2 * Hc + h],   ghn = bhh[2 * Hc + h];
#pragma unroll
    for (int z = 0; z < 4; z++) {
        const float* gi = g_gip + (size_t)(z * 64 + b) * (3 * Hc);
        const float* gh = g_ghp + (size_t)(z * 64 + b) * (3 * Hc);
        gir += gi[h];          ghr += gh[h];
        giz += gi[Hc + h];     ghz += gh[Hc + h];
        gin += gi[2 * Hc + h]; ghn += gh[2 * Hc + h];
    }
    float r = 1.0f / (1.0f + expf(-(gir + ghr)));
    float z = 1.0f / (1.0f + expf(-(giz + ghz)));
    float n = tanhf(gin + r * ghn);
    float hp = hidden[g];
    hnew[g] = (1.0f - z) * n + z * hp;
}

// ===========================================================================
extern "C" void kernel_launch(void* const* d_in, const int* in_sizes, int n_in,
                              void* d_out, int out_size)
{
    const int*   input    = (const int*)d_in[0];
    const float* hidden   = (const float*)d_in[1];
    const float* enc      = (const float*)d_in[2];
    const float* emb      = (const float*)d_in[3];
    const float* attn_w_W = (const float*)d_in[4];
    const float* attn_w_b = (const float*)d_in[5];
    const float* attn_v_W = (const float*)d_in[6];
    // d_in[7] = attn_v_b : softmax-invariant, skipped
    const float* gru_Wih  = (const float*)d_in[8];
    const float* gru_Whh  = (const float*)d_in[9];
    const float* gru_bih  = (const float*)d_in[10];
    const float* gru_bhh  = (const float*)d_in[11];
    const float* out_W    = (const float*)d_in[12];
    const float* out_b    = (const float*)d_in[13];

    float* out    = (float*)d_out;
    float* logits = out;                        // B*V
    float* hnew   = out + (size_t)Bc * Vc;      // B*H
    float* wts    = hnew + (size_t)Bc * Hc;     // S*B

    float *p_hWhp, *p_gx, *p_gip, *p_ghp;
    cudaGetSymbolAddress((void**)&p_hWhp, g_hWhp);
    cudaGetSymbolAddress((void**)&p_gx,   g_x);
    cudaGetSymbolAddress((void**)&p_gip,  g_gip);
    cudaGetSymbolAddress((void**)&p_ghp,  g_ghp);

    cudaFuncSetAttribute(attn_score_tc, cudaFuncAttributeMaxDynamicSharedMemorySize, ATT_SMEM);
    cudaFuncSetAttribute(gemm_wact_tc,  cudaFuncAttributeMaxDynamicSharedMemorySize, LG_SMEM);

    // 1. combined: hWh partials + gh partials (exact fp32 split-K)
    splitk_pre<<<dim3(64, 1, 4), 256>>>(attn_w_W, hidden, gru_Whh, p_hWhp, p_ghp);
    // 2. reduce + bias -> g_hWh
    hwh_reduce<<<256, 256>>>(attn_w_b);
    // 3. fused attention scores (tf32 tensor + tanh + v-dot)
    attn_score_tc<<<dim3(8, 256), 256, ATT_SMEM>>>(enc, attn_w_W, attn_v_W);
    // 4. softmax -> attn_weights (output region 3)
    softmax_kernel<<<Bc, 256>>>(wts);
    // 5. context + embedding (1024 CTAs)
    ctx_kernel<<<dim3(16, Bc), 256>>>(enc, input, emb, wts);
    // 6. gi split-K partials (exact fp32)
    splitk_gi<<<dim3(48, 1, 4), 256>>>(gru_Wih, p_gx, p_gip);
    // 7. GRU combine (sums partials) -> h_new (output region 2)
    gru_kernel<<<Bc * Hc / 256, 256>>>(hidden, hnew, gru_bih, gru_bhh);
    // 8. logits = h_new @ out_W^T + out_b (3-term split-tf32, 3-stage pipeline)
    gemm_wact_tc<<<Vc / 128, 256, LG_SMEM>>>(out_W, Hc, hnew, logits, Vc, out_b);
}

// round 10
// speedup vs baseline: 1.2439x; 1.0695x over previous
#include <cuda_runtime.h>
#include <cstdint>
#include <cstddef>

#define Bc 64
#define Sc 512
#define Hc 1024
#define Vc 32000
#define SB (Sc * Bc)

// ---------------- scratch (device globals, no allocation) ----------------
__device__ float g_hWh[Bc * Hc];         // reduced: [b][h] hidden@W_h^T + attn_w_b
__device__ float g_hWhp[4 * Bc * Hc];    // split-K partials
__device__ float g_spart[SB * 16];       // 16 partial scores per row r = s*B+b
__device__ float g_x[Bc * 2 * Hc];       // [b][emb ; context]
__device__ float g_gip[4 * Bc * 3 * Hc]; // gi split-K partials [z][b][3H]
__device__ float g_ghp[4 * Bc * 3 * Hc]; // gh split-K partials [z][b][3H]

// ---------------- portable-PTX helpers ----------------
__device__ __forceinline__ uint32_t smem_u32(const void* p) {
    uint32_t a;
    asm("{ .reg .u64 t; cvta.to.shared.u64 t, %1; cvt.u32.u64 %0, t; }"
        : "=r"(a) : "l"(p));
    return a;
}
#define CPA(dst, src) \
    asm volatile("cp.async.cg.shared.global [%0], [%1], 16;" :: "r"(dst), "l"(src))
#define CPCOMMIT() asm volatile("cp.async.commit_group;" ::: "memory")
#define CPWAIT(n)  asm volatile("cp.async.wait_group %0;" :: "n"(n) : "memory")

__device__ __forceinline__ void mma_tf32(float* c, const uint32_t* a, const uint32_t* b) {
    asm volatile(
        "mma.sync.aligned.m16n8k8.row.col.f32.tf32.tf32.f32 "
        "{%0,%1,%2,%3}, {%4,%5,%6,%7}, {%8,%9}, {%0,%1,%2,%3};"
        : "+f"(c[0]), "+f"(c[1]), "+f"(c[2]), "+f"(c[3])
        : "r"(a[0]), "r"(a[1]), "r"(a[2]), "r"(a[3]), "r"(b[0]), "r"(b[1]));
}
__device__ __forceinline__ void split_tf32(float x, uint32_t& hi, uint32_t& lo) {
    uint32_t h = __float_as_uint(x) & 0xFFFFE000u;
    hi = h;
    lo = __float_as_uint(x - __uint_as_float(h));   // exact (same exponent)
}

// ===========================================================================
// Attention score kernel (mma.sync tf32). CTA tile 128x128, FOUR warps of
// 64x64 (128 threads) -> 1.0 LDS per MMA (was 1.5). 3-stage pipeline,
// K=32 per stage, static buffers via manual unroll-by-3, ONE sync/iter,
// 2 CTAs/SM.
// ===========================================================================
#define ATT_SMEM 110592

__global__ void __launch_bounds__(128, 2)
attn_score_tc(const float* __restrict__ enc, const float* __restrict__ W,
              const float* __restrict__ vvec)
{
    extern __shared__ float sm[];
    const int tid = threadIdx.x, lane = tid & 31, wid = tid >> 5;
    const int n0 = blockIdx.x * 128, m0 = blockIdx.y * 128;
    const int wm = (wid >> 1) * 64, wn = (wid & 1) * 64;
    const float* Wp = W + Hc;
    const uint32_t sbase = smem_u32(sm);
    const int fr = lane >> 2, fc = lane & 3;

    float acc[4][8][4] = {};

#define LOAD_STAGE(buf, kk)                                                   \
    do {                                                                      \
        const uint32_t db = sbase + (buf) * 36864u;                           \
        _Pragma("unroll")                                                     \
        for (int i_ = 0; i_ < 8; i_++) {                                      \
            int c_ = i_ * 128 + tid;                                          \
            int row_ = c_ >> 3, kc_ = c_ & 7;                                 \
            CPA(db + (row_ * 36 + kc_ * 4) * 4,                               \
                enc + (size_t)(m0 + row_) * Hc + (kk) + kc_ * 4);             \
            CPA(db + 18432u + (row_ * 36 + kc_ * 4) * 4,                      \
                Wp + (size_t)(n0 + row_) * (2 * Hc) + (kk) + kc_ * 4);        \
        }                                                                     \
        CPCOMMIT();                                                           \
    } while (0)

#define STEP(ks, buf)                                                         \
    do {                                                                      \
        CPWAIT(1);                                                            \
        __syncthreads();                                                      \
        if ((ks) + 2 < 32) LOAD_STAGE(((ks) + 2) % 3, ((ks) + 2) * 32);       \
        else               CPCOMMIT();                                        \
        const float* Sa = sm + (buf) * 9216;                                  \
        const float* Sb = Sa + 4608;                                          \
        _Pragma("unroll")                                                     \
        for (int kh = 0; kh < 4; kh++) {                                      \
            const int k8 = kh * 8;                                            \
            uint32_t a[4][4], b[8][2];                                        \
            _Pragma("unroll")                                                 \
            for (int mi = 0; mi < 4; mi++) {                                  \
                const float* ap = Sa + (wm + 16 * mi + fr) * 36 + k8 + fc;    \
                a[mi][0] = __float_as_uint(ap[0]);                            \
                a[mi][1] = __float_as_uint(ap[288]);                          \
                a[mi][2] = __float_as_uint(ap[4]);                            \
                a[mi][3] = __float_as_uint(ap[292]);                          \
            }                                                                 \
            _Pragma("unroll")                                                 \
            for (int nj = 0; nj < 8; nj++) {                                  \
                const float* bp = Sb + (wn + 8 * nj + fr) * 36 + k8 + fc;     \
                b[nj][0] = __float_as_uint(bp[0]);                            \
                b[nj][1] = __float_as_uint(bp[4]);                            \
            }                                                                 \
            _Pragma("unroll")                                                 \
            for (int mi = 0; mi < 4; mi++)                                    \
                _Pragma("unroll")                                             \
                for (int nj = 0; nj < 8; nj++)                                \
                    mma_tf32(acc[mi][nj], a[mi], b[nj]);                      \
        }                                                                     \
    } while (0)

    LOAD_STAGE(0, 0);
    LOAD_STAGE(1, 32);

    for (int ks = 0; ks < 30; ks += 3) {
        STEP(ks + 0, 0);
        STEP(ks + 1, 1);
        STEP(ks + 2, 2);
    }
    STEP(30, 0);
    STEP(31, 1);
#undef STEP
#undef LOAD_STAGE
    __syncthreads();

    // ---- epilogue: stage hWh slice (stride 133, conflict-free) + v slice ----
    float* shf = sm;
    float* shv = sm + 64 * 133;
    for (int j = tid; j < 2048; j += 128) {      // 2048 float4 = 64x128 floats
        int row = j >> 5, seg = j & 31;
        float4 v = *(const float4*)(g_hWh + (size_t)row * Hc + n0 + seg * 4);
        float* d = &shf[row * 133 + seg * 4];
        d[0] = v.x; d[1] = v.y; d[2] = v.z; d[3] = v.w;
    }
    shv[tid] = vvec[n0 + tid];
    __syncthreads();

    const int c2 = (lane & 3) * 2;
    float s[4][2] = {};
#pragma unroll
    for (int mi = 0; mi < 4; mi++) {
        const int R0 = wm + 16 * mi + fr;
        const int b0 = R0 & 63, b1 = (R0 + 8) & 63;
#pragma unroll
        for (int nj = 0; nj < 8; nj++) {
            const int n = wn + 8 * nj + c2;
            const float v0 = shv[n], v1 = shv[n + 1];
            s[mi][0] += tanhf(acc[mi][nj][0] + shf[b0 * 133 + n]) * v0
                      + tanhf(acc[mi][nj][1] + shf[b0 * 133 + n + 1]) * v1;
            s[mi][1] += tanhf(acc[mi][nj][2] + shf[b1 * 133 + n]) * v0
                      + tanhf(acc[mi][nj][3] + shf[b1 * 133 + n + 1]) * v1;
        }
    }
#pragma unroll
    for (int mi = 0; mi < 4; mi++)
#pragma unroll
        for (int h = 0; h < 2; h++) {
            s[mi][h] += __shfl_xor_sync(0xffffffffu, s[mi][h], 1);
            s[mi][h] += __shfl_xor_sync(0xffffffffu, s[mi][h], 2);
        }
    if ((lane & 3) == 0) {
        const int col = blockIdx.x * 2 + (wid & 1);
#pragma unroll
        for (int mi = 0; mi < 4; mi++) {
            const int R0 = wm + 16 * mi + fr;
            g_spart[(size_t)(m0 + R0) * 16 + col]     = s[mi][0];
            g_spart[(size_t)(m0 + R0 + 8) * 16 + col] = s[mi][1];
        }
    }
}

// ===========================================================================
// Exact fp32 SIMT split-K GEMM body (device function).
// ===========================================================================
__device__ __forceinline__ void splitk_body(
    const float* __restrict__ A, int lda,
    const float* __restrict__ act, int ldact,
    float* __restrict__ Cpart, int M, int Ks, int m0, int z)
{
    __shared__ float As[16][68];
    __shared__ float Bs[16][68];
    const int tid = threadIdx.x;

    const int lrow = tid >> 2, lk = (tid & 3) * 4;
    const float* Ap = A + (size_t)(m0 + lrow) * lda + z * Ks + lk;
    const float* Bp = act + (size_t)lrow * ldact + z * Ks + lk;

    const int ty = tid >> 4, tx = tid & 15;
    float acc[4][4] = {};

    for (int k0 = 0; k0 < Ks; k0 += 16) {
        float4 av = *(const float4*)(Ap + k0);
        float4 bv = *(const float4*)(Bp + k0);
        As[lk + 0][lrow] = av.x; As[lk + 1][lrow] = av.y;
        As[lk + 2][lrow] = av.z; As[lk + 3][lrow] = av.w;
        Bs[lk + 0][lrow] = bv.x; Bs[lk + 1][lrow] = bv.y;
        Bs[lk + 2][lrow] = bv.z; Bs[lk + 3][lrow] = bv.w;
        __syncthreads();
#pragma unroll
        for (int k = 0; k < 16; k++) {
            float4 a = *(const float4*)&As[k][ty * 4];
            float4 b = *(const float4*)&Bs[k][tx * 4];
            float ar[4] = {a.x, a.y, a.z, a.w};
            float br[4] = {b.x, b.y, b.z, b.w};
#pragma unroll
            for (int i = 0; i < 4; i++)
#pragma unroll
                for (int j = 0; j < 4; j++)
                    acc[i][j] += ar[i] * br[j];
        }
        __syncthreads();
    }

#pragma unroll
    for (int i = 0; i < 4; i++)
#pragma unroll
        for (int j = 0; j < 4; j++)
            Cpart[(size_t)(z * 64 + tx * 4 + j) * M + m0 + ty * 4 + i] = acc[i][j];
}

// Combined pre-attention split-K launch: hWh partials (bx<16) + gh partials.
__global__ void __launch_bounds__(256)
splitk_pre(const float* __restrict__ attn_w_W, const float* __restrict__ hidden,
           const float* __restrict__ gru_Whh,
           float* __restrict__ hWhp, float* __restrict__ ghp)
{
    const int bx = blockIdx.x, z = blockIdx.z;
    if (bx < 16)
        splitk_body(attn_w_W, 2 * Hc, hidden, Hc, hWhp, Hc, 256, bx * 64, z);
    else
        splitk_body(gru_Whh, Hc, hidden, Hc, ghp, 3 * Hc, 256, (bx - 16) * 64, z);
}

// gi partials (post-context)
__global__ void __launch_bounds__(256)
splitk_gi(const float* __restrict__ gru_Wih, const float* __restrict__ x,
          float* __restrict__ gip)
{
    splitk_body(gru_Wih, 2 * Hc, x, 2 * Hc, gip, 3 * Hc, 512, blockIdx.x * 64, blockIdx.z);
}

// Reduce hWh partials + attn_w_b -> g_hWh
__global__ void __launch_bounds__(256)
hwh_reduce(const float* __restrict__ awb)
{
    const int idx = blockIdx.x * 256 + threadIdx.x;   // 65536
    const int b = idx >> 10, h = idx & 1023;
    float v = awb[h];
#pragma unroll
    for (int z = 0; z < 4; z++) v += g_hWhp[(size_t)(z * 64 + b) * Hc + h];
    g_hWh[idx] = v;
}

// ===========================================================================
// Logits GEMM: 2-term split-tf32 (B split into hi+lo; A HW-truncated).
// 3-stage K=32 static-unroll-3 one-sync pipeline (R9 proven).
// ===========================================================================
#define LG_SMEM 82944

__global__ void __launch_bounds__(256, 2)
gemm_wact_tc(const float* __restrict__ A, int lda,
             const float* __restrict__ act,
             float* __restrict__ C, int ldc,
             const float* __restrict__ bias)
{
    extern __shared__ float sm[];
    const int tid = threadIdx.x, lane = tid & 31, wid = tid >> 5;
    const int m0 = blockIdx.x * 128;
    const int wm = (wid & 3) * 32, wn = (wid >> 2) * 32;
    const uint32_t sbase = smem_u32(sm);
    const int fr = lane >> 2, fc = lane & 3;

    float acc[2][4][4] = {};

#define LG_LOAD(buf, kk)                                                      \
    do {                                                                      \
        const uint32_t db = sbase + (buf) * 27648u;                           \
        _Pragma("unroll")                                                     \
        for (int i_ = 0; i_ < 4; i_++) {                                      \
            int c_ = i_ * 256 + tid;                                          \
            int row_ = c_ >> 3, kc_ = c_ & 7;                                 \
            CPA(db + (row_ * 36 + kc_ * 4) * 4,                               \
                A + (size_t)(m0 + row_) * lda + (kk) + kc_ * 4);              \
        }                                                                     \
        _Pragma("unroll")                                                     \
        for (int i_ = 0; i_ < 2; i_++) {                                      \
            int c_ = i_ * 256 + tid;                                          \
            int row_ = c_ >> 3, kc_ = c_ & 7;                                 \
            CPA(db + 18432u + (row_ * 36 + kc_ * 4) * 4,                      \
                act + (size_t)row_ * Hc + (kk) + kc_ * 4);                    \
        }                                                                     \
        CPCOMMIT();                                                           \
    } while (0)

#define LG_STEP(ks, buf)                                                      \
    do {                                                                      \
        CPWAIT(1);                                                            \
        __syncthreads();                                                      \
        if ((ks) + 2 < 32) LG_LOAD(((ks) + 2) % 3, ((ks) + 2) * 32);          \
        else               CPCOMMIT();                                        \
        const float* Sa = sm + (buf) * 6912;                                  \
        const float* Sb = Sa + 4608;                                          \
        _Pragma("unroll")                                                     \
        for (int kh = 0; kh < 4; kh++) {                                      \
            const int k8 = kh * 8;                                            \
            uint32_t a[2][4], bh[4][2], bl[4][2];                             \
            _Pragma("unroll")                                                 \
            for (int mi = 0; mi < 2; mi++) {                                  \
                const float* ap = Sa + (wm + 16 * mi + fr) * 36 + k8 + fc;    \
                a[mi][0] = __float_as_uint(ap[0]);                            \
                a[mi][1] = __float_as_uint(ap[288]);                          \
                a[mi][2] = __float_as_uint(ap[4]);                            \
                a[mi][3] = __float_as_uint(ap[292]);                          \
            }                                                                 \
            _Pragma("unroll")                                                 \
            for (int nj = 0; nj < 4; nj++) {                                  \
                const float* bp = Sb + (wn + 8 * nj + fr) * 36 + k8 + fc;     \
                split_tf32(bp[0], bh[nj][0], bl[nj][0]);                      \
                split_tf32(bp[4], bh[nj][1], bl[nj][1]);                      \
            }                                                                 \
            _Pragma("unroll")                                                 \
            for (int mi = 0; mi < 2; mi++)                                    \
                _Pragma("unroll")                                             \
                for (int nj = 0; nj < 4; nj++) {                              \
                    mma_tf32(acc[mi][nj], a[mi], bl[nj]);                     \
                    mma_tf32(acc[mi][nj], a[mi], bh[nj]);                     \
                }                                                             \
        }                                                                     \
    } while (0)

    LG_LOAD(0, 0);
    LG_LOAD(1, 32);

    for (int ks = 0; ks < 30; ks += 3) {
        LG_STEP(ks + 0, 0);
        LG_STEP(ks + 1, 1);
        LG_STEP(ks + 2, 2);
    }
    LG_STEP(30, 0);
    LG_STEP(31, 1);
#undef LG_STEP
#undef LG_LOAD

    const int c2 = (lane & 3) * 2;
#pragma unroll
    for (int mi = 0; mi < 2; mi++) {
        const int m = m0 + wm + 16 * mi + fr;
        const float bm0 = bias[m], bm1 = bias[m + 8];
#pragma unroll
        for (int nj = 0; nj < 4; nj++) {
            const int n = wn + 8 * nj + c2;
            C[(size_t)n * ldc + m]           = acc[mi][nj][0] + bm0;
            C[(size_t)(n + 1) * ldc + m]     = acc[mi][nj][1] + bm0;
            C[(size_t)n * ldc + m + 8]       = acc[mi][nj][2] + bm1;
            C[(size_t)(n + 1) * ldc + m + 8] = acc[mi][nj][3] + bm1;
        }
    }
}

// ===========================================================================
// Softmax over seq (512) per batch; writes attn_weights (output region 3).
// ===========================================================================
__global__ void __launch_bounds__(256)
softmax_kernel(float* __restrict__ wout)
{
    __shared__ float sc[Sc];
    __shared__ float red[256];
    const int b = blockIdx.x, tid = threadIdx.x;

    for (int s = tid; s < Sc; s += 256) {
        const float4* p = (const float4*)&g_spart[(size_t)(s * Bc + b) * 16];
        float v = 0.0f;
#pragma unroll
        for (int i = 0; i < 4; i++) {
            float4 q = p[i];
            v += q.x + q.y + q.z + q.w;
        }
        sc[s] = v;
    }
    __syncthreads();

    float m = fmaxf(sc[tid], sc[tid + 256]);
    red[tid] = m;
    __syncthreads();
    for (int st = 128; st > 0; st >>= 1) {
        if (tid < st) red[tid] = fmaxf(red[tid], red[tid + st]);
        __syncthreads();
    }
    float mx = red[0];
    __syncthreads();

    float e0 = expf(sc[tid] - mx);
    float e1 = expf(sc[tid + 256] - mx);
    red[tid] = e0 + e1;
    __syncthreads();
    for (int st = 128; st > 0; st >>= 1) {
        if (tid < st) red[tid] += red[tid + st];
        __syncthreads();
    }
    float inv = 1.0f / red[0];

    wout[(size_t)tid * Bc + b]         = e0 * inv;
    wout[(size_t)(tid + 256) * Bc + b] = e1 * inv;
}

// ===========================================================================
// Context + embedding. grid (16 k-chunks, 64 b), 256 threads.
// ===========================================================================
__global__ void __launch_bounds__(256)
ctx_kernel(const float* __restrict__ enc, const int* __restrict__ input,
           const float* __restrict__ emb, const float* __restrict__ wts)
{
    __shared__ float w[Sc];
    __shared__ float part[4][64];
    const int kc = blockIdx.x, b = blockIdx.y, tid = threadIdx.x;

    w[tid]       = wts[(size_t)tid * Bc + b];
    w[tid + 256] = wts[(size_t)(tid + 256) * Bc + b];

    const int kk = tid & 63, sg = tid >> 6;
    const int k = kc * 64 + kk;

    if (sg == 3) {   // embedding copy for this CTA's 64-k slice
        const int idx = input[b];
        g_x[(size_t)b * 2 * Hc + k] = emb[(size_t)idx * Hc + k];
    }
    __syncthreads();

    const float* p = enc + ((size_t)(sg * 128) * Bc + b) * Hc + k;
    const float* wp = w + sg * 128;
    float acc = 0.0f;
#pragma unroll 8
    for (int s = 0; s < 128; s++)
        acc += wp[s] * p[(size_t)s * (Bc * Hc)];
    part[sg][kk] = acc;
    __syncthreads();

    if (tid < 64)
        g_x[(size_t)b * 2 * Hc + Hc + kc * 64 + tid] =
            (part[0][tid] + part[1][tid]) + (part[2][tid] + part[3][tid]);
}

// GRU gate combine: sums the 4 split-K partials of gi/gh inline (exact fp32).
__global__ void __launch_bounds__(256)
gru_kernel(const float* __restrict__ hidden, float* __restrict__ hnew,
           const float* __restrict__ bih, const float* __restrict__ bhh)
{
    const int g = blockIdx.x * 256 + threadIdx.x;   // 65536
    const int b = g >> 10, h = g & 1023;

    float gir = bih[h],            ghr = bhh[h];
    float giz = bih[Hc + h],       ghz = bhh[Hc + h];
    float gin = bih[2 * Hc + h],   ghn = bhh[2 * Hc + h];
#pragma unroll
    for (int z = 0; z < 4; z++) {
        const float* gi = g_gip + (size_t)(z * 64 + b) * (3 * Hc);
        const float* gh = g_ghp + (size_t)(z * 64 + b) * (3 * Hc);
        gir += gi[h];          ghr += gh[h];
        giz += gi[Hc + h];     ghz += gh[Hc + h];
        gin += gi[2 * Hc + h]; ghn += gh[2 * Hc + h];
    }
    float r = 1.0f / (1.0f + expf(-(gir + ghr)));
    float z = 1.0f / (1.0f + expf(-(giz + ghz)));
    float n = tanhf(gin + r * ghn);
    float hp = hidden[g];
    hnew[g] = (1.0f - z) * n + z * hp;
}

// ===========================================================================
extern "C" void kernel_launch(void* const* d_in, const int* in_sizes, int n_in,
                              void* d_out, int out_size)
{
    const int*   input    = (const int*)d_in[0];
    const float* hidden   = (const float*)d_in[1];
    const float* enc      = (const float*)d_in[2];
    const float* emb      = (const float*)d_in[3];
    const float* attn_w_W = (const float*)d_in[4];
    const float* attn_w_b = (const float*)d_in[5];
    const float* attn_v_W = (const float*)d_in[6];
    // d_in[7] = attn_v_b : softmax-invariant, skipped
    const float* gru_Wih  = (const float*)d_in[8];
    const float* gru_Whh  = (const float*)d_in[9];
    const float* gru_bih  = (const float*)d_in[10];
    const float* gru_bhh  = (const float*)d_in[11];
    const float* out_W    = (const float*)d_in[12];
    const float* out_b    = (const float*)d_in[13];

    float* out    = (float*)d_out;
    float* logits = out;                        // B*V
    float* hnew   = out + (size_t)Bc * Vc;      // B*H
    float* wts    = hnew + (size_t)Bc * Hc;     // S*B

    float *p_hWhp, *p_gx, *p_gip, *p_ghp;
    cudaGetSymbolAddress((void**)&p_hWhp, g_hWhp);
    cudaGetSymbolAddress((void**)&p_gx,   g_x);
    cudaGetSymbolAddress((void**)&p_gip,  g_gip);
    cudaGetSymbolAddress((void**)&p_ghp,  g_ghp);

    cudaFuncSetAttribute(attn_score_tc, cudaFuncAttributeMaxDynamicSharedMemorySize, ATT_SMEM);
    cudaFuncSetAttribute(gemm_wact_tc,  cudaFuncAttributeMaxDynamicSharedMemorySize, LG_SMEM);

    // 1. combined: hWh partials + gh partials (exact fp32 split-K)
    splitk_pre<<<dim3(64, 1, 4), 256>>>(attn_w_W, hidden, gru_Whh, p_hWhp, p_ghp);
    // 2. reduce + bias -> g_hWh
    hwh_reduce<<<256, 256>>>(attn_w_b);
    // 3. fused attention scores (tf32 tensor + tanh + v-dot), 4-warp 64x64 tiles
    attn_score_tc<<<dim3(8, 256), 128, ATT_SMEM>>>(enc, attn_w_W, attn_v_W);
    // 4. softmax -> attn_weights (output region 3)
    softmax_kernel<<<Bc, 256>>>(wts);
    // 5. context + embedding (1024 CTAs)
    ctx_kernel<<<dim3(16, Bc), 256>>>(enc, input, emb, wts);
    // 6. gi split-K partials (exact fp32)
    splitk_gi<<<dim3(48, 1, 4), 256>>>(gru_Wih, p_gx, p_gip);
    // 7. GRU combine (sums partials) -> h_new (output region 2)
    gru_kernel<<<Bc * Hc / 256, 256>>>(hidden, hnew, gru_bih, gru_bhh);
    // 8. logits = h_new @ out_W^T + out_b (2-term split-tf32, output region 1)
    gemm_wact_tc<<<Vc / 128, 256, LG_SMEM>>>(out_W, Hc, hnew, logits, Vc, out_b);
}

// round 11
// speedup vs baseline: 1.2692x; 1.0203x over previous
#include <cuda_runtime.h>
#include <cstdint>
#include <cstddef>

#define Bc 64
#define Sc 512
#define Hc 1024
#define Vc 32000
#define SB (Sc * Bc)

// ---------------- scratch (device globals, no allocation) ----------------
__device__ float g_hWhp[4 * Bc * Hc];    // hWh split-K partials [z][b][h]
__device__ float g_spart[SB * 16];       // 16 partial scores per row r = s*B+b
__device__ float g_ctx[Bc * Hc];         // context [b][h]
__device__ float g_gip[8 * Bc * 3 * Hc]; // gi partials: z0-3 emb-half, z4-7 ctx-half
__device__ float g_ghp[4 * Bc * 3 * Hc]; // gh split-K partials [z][b][3H]

// ---------------- portable-PTX helpers ----------------
__device__ __forceinline__ uint32_t smem_u32(const void* p) {
    uint32_t a;
    asm("{ .reg .u64 t; cvta.to.shared.u64 t, %1; cvt.u32.u64 %0, t; }"
        : "=r"(a) : "l"(p));
    return a;
}
#define CPA(dst, src) \
    asm volatile("cp.async.cg.shared.global [%0], [%1], 16;" :: "r"(dst), "l"(src))
#define CPCOMMIT() asm volatile("cp.async.commit_group;" ::: "memory")
#define CPWAIT(n)  asm volatile("cp.async.wait_group %0;" :: "n"(n) : "memory")

__device__ __forceinline__ void mma_tf32(float* c, const uint32_t* a, const uint32_t* b) {
    asm volatile(
        "mma.sync.aligned.m16n8k8.row.col.f32.tf32.tf32.f32 "
        "{%0,%1,%2,%3}, {%4,%5,%6,%7}, {%8,%9}, {%0,%1,%2,%3};"
        : "+f"(c[0]), "+f"(c[1]), "+f"(c[2]), "+f"(c[3])
        : "r"(a[0]), "r"(a[1]), "r"(a[2]), "r"(a[3]), "r"(b[0]), "r"(b[1]));
}
__device__ __forceinline__ void split_tf32(float x, uint32_t& hi, uint32_t& lo) {
    uint32_t h = __float_as_uint(x) & 0xFFFFE000u;
    hi = h;
    lo = __float_as_uint(x - __uint_as_float(h));   // exact (same exponent)
}

// ===========================================================================
// Attention score kernel (mma.sync tf32). CTA tile 128x128, FOUR warps of
// 64x64 (128 threads). 3-stage K=32 pipeline, static buffers via manual
// unroll-by-3, ONE sync/iter, 2 CTAs/SM.  [R10 proven mainloop — frozen]
// Epilogue now sums the 4 hWh partials + bias directly (hwh_reduce deleted).
// ===========================================================================
#define ATT_SMEM 110592

__global__ void __launch_bounds__(128, 2)
attn_score_tc(const float* __restrict__ enc, const float* __restrict__ W,
              const float* __restrict__ vvec, const float* __restrict__ awb)
{
    extern __shared__ float sm[];
    const int tid = threadIdx.x, lane = tid & 31, wid = tid >> 5;
    const int n0 = blockIdx.x * 128, m0 = blockIdx.y * 128;
    const int wm = (wid >> 1) * 64, wn = (wid & 1) * 64;
    const float* Wp = W + Hc;
    const uint32_t sbase = smem_u32(sm);
    const int fr = lane >> 2, fc = lane & 3;

    float acc[4][8][4] = {};

#define LOAD_STAGE(buf, kk)                                                   \
    do {                                                                      \
        const uint32_t db = sbase + (buf) * 36864u;                           \
        _Pragma("unroll")                                                     \
        for (int i_ = 0; i_ < 8; i_++) {                                      \
            int c_ = i_ * 128 + tid;                                          \
            int row_ = c_ >> 3, kc_ = c_ & 7;                                 \
            CPA(db + (row_ * 36 + kc_ * 4) * 4,                               \
                enc + (size_t)(m0 + row_) * Hc + (kk) + kc_ * 4);             \
            CPA(db + 18432u + (row_ * 36 + kc_ * 4) * 4,                      \
                Wp + (size_t)(n0 + row_) * (2 * Hc) + (kk) + kc_ * 4);        \
        }                                                                     \
        CPCOMMIT();                                                           \
    } while (0)

#define STEP(ks, buf)                                                         \
    do {                                                                      \
        CPWAIT(1);                                                            \
        __syncthreads();                                                      \
        if ((ks) + 2 < 32) LOAD_STAGE(((ks) + 2) % 3, ((ks) + 2) * 32);       \
        else               CPCOMMIT();                                        \
        const float* Sa = sm + (buf) * 9216;                                  \
        const float* Sb = Sa + 4608;                                          \
        _Pragma("unroll")                                                     \
        for (int kh = 0; kh < 4; kh++) {                                      \
            const int k8 = kh * 8;                                            \
            uint32_t a[4][4], b[8][2];                                        \
            _Pragma("unroll")                                                 \
            for (int mi = 0; mi < 4; mi++) {                                  \
                const float* ap = Sa + (wm + 16 * mi + fr) * 36 + k8 + fc;    \
                a[mi][0] = __float_as_uint(ap[0]);                            \
                a[mi][1] = __float_as_uint(ap[288]);                          \
                a[mi][2] = __float_as_uint(ap[4]);                            \
                a[mi][3] = __float_as_uint(ap[292]);                          \
            }                                                                 \
            _Pragma("unroll")                                                 \
            for (int nj = 0; nj < 8; nj++) {                                  \
                const float* bp = Sb + (wn + 8 * nj + fr) * 36 + k8 + fc;     \
                b[nj][0] = __float_as_uint(bp[0]);                            \
                b[nj][1] = __float_as_uint(bp[4]);                            \
            }                                                                 \
            _Pragma("unroll")                                                 \
            for (int mi = 0; mi < 4; mi++)                                    \
                _Pragma("unroll")                                             \
                for (int nj = 0; nj < 8; nj++)                                \
                    mma_tf32(acc[mi][nj], a[mi], b[nj]);                      \
        }                                                                     \
    } while (0)

    LOAD_STAGE(0, 0);
    LOAD_STAGE(1, 32);

    for (int ks = 0; ks < 30; ks += 3) {
        STEP(ks + 0, 0);
        STEP(ks + 1, 1);
        STEP(ks + 2, 2);
    }
    STEP(30, 0);
    STEP(31, 1);
#undef STEP
#undef LOAD_STAGE
    __syncthreads();

    // ---- epilogue: stage (bias + sum of 4 hWh partials), stride 133 ----
    float* shf = sm;
    float* shv = sm + 64 * 133;
    for (int j = tid; j < 2048; j += 128) {      // 2048 float4 = 64x128 floats
        int row = j >> 5, seg = j & 31;
        float4 v = *(const float4*)(awb + n0 + seg * 4);
#pragma unroll
        for (int z = 0; z < 4; z++) {
            float4 p = *(const float4*)(g_hWhp + (size_t)(z * 64 + row) * Hc + n0 + seg * 4);
            v.x += p.x; v.y += p.y; v.z += p.z; v.w += p.w;
        }
        float* d = &shf[row * 133 + seg * 4];
        d[0] = v.x; d[1] = v.y; d[2] = v.z; d[3] = v.w;
    }
    shv[tid] = vvec[n0 + tid];
    __syncthreads();

    const int c2 = (lane & 3) * 2;
    float s[4][2] = {};
#pragma unroll
    for (int mi = 0; mi < 4; mi++) {
        const int R0 = wm + 16 * mi + fr;
        const int b0 = R0 & 63, b1 = (R0 + 8) & 63;
#pragma unroll
        for (int nj = 0; nj < 8; nj++) {
            const int n = wn + 8 * nj + c2;
            const float v0 = shv[n], v1 = shv[n + 1];
            s[mi][0] += tanhf(acc[mi][nj][0] + shf[b0 * 133 + n]) * v0
                      + tanhf(acc[mi][nj][1] + shf[b0 * 133 + n + 1]) * v1;
            s[mi][1] += tanhf(acc[mi][nj][2] + shf[b1 * 133 + n]) * v0
                      + tanhf(acc[mi][nj][3] + shf[b1 * 133 + n + 1]) * v1;
        }
    }
#pragma unroll
    for (int mi = 0; mi < 4; mi++)
#pragma unroll
        for (int h = 0; h < 2; h++) {
            s[mi][h] += __shfl_xor_sync(0xffffffffu, s[mi][h], 1);
            s[mi][h] += __shfl_xor_sync(0xffffffffu, s[mi][h], 2);
        }
    if ((lane & 3) == 0) {
        const int col = blockIdx.x * 2 + (wid & 1);
#pragma unroll
        for (int mi = 0; mi < 4; mi++) {
            const int R0 = wm + 16 * mi + fr;
            g_spart[(size_t)(m0 + R0) * 16 + col]     = s[mi][0];
            g_spart[(size_t)(m0 + R0 + 8) * 16 + col] = s[mi][1];
        }
    }
}

// ===========================================================================
// Exact fp32 SIMT split-K GEMM bodies.
// ===========================================================================
__device__ __forceinline__ void splitk_body(
    const float* __restrict__ A, int lda,
    const float* __restrict__ act, int ldact,
    float* __restrict__ Cpart, int M, int Ks, int m0, int z)
{
    __shared__ float As[16][68];
    __shared__ float Bs[16][68];
    const int tid = threadIdx.x;

    const int lrow = tid >> 2, lk = (tid & 3) * 4;
    const float* Ap = A + (size_t)(m0 + lrow) * lda + z * Ks + lk;
    const float* Bp = act + (size_t)lrow * ldact + z * Ks + lk;

    const int ty = tid >> 4, tx = tid & 15;
    float acc[4][4] = {};

    for (int k0 = 0; k0 < Ks; k0 += 16) {
        float4 av = *(const float4*)(Ap + k0);
        float4 bv = *(const float4*)(Bp + k0);
        As[lk + 0][lrow] = av.x; As[lk + 1][lrow] = av.y;
        As[lk + 2][lrow] = av.z; As[lk + 3][lrow] = av.w;
        Bs[lk + 0][lrow] = bv.x; Bs[lk + 1][lrow] = bv.y;
        Bs[lk + 2][lrow] = bv.z; Bs[lk + 3][lrow] = bv.w;
        __syncthreads();
#pragma unroll
        for (int k = 0; k < 16; k++) {
            float4 a = *(const float4*)&As[k][ty * 4];
            float4 b = *(const float4*)&Bs[k][tx * 4];
            float ar[4] = {a.x, a.y, a.z, a.w};
            float br[4] = {b.x, b.y, b.z, b.w};
#pragma unroll
            for (int i = 0; i < 4; i++)
#pragma unroll
                for (int j = 0; j < 4; j++)
                    acc[i][j] += ar[i] * br[j];
        }
        __syncthreads();
    }

#pragma unroll
    for (int i = 0; i < 4; i++)
#pragma unroll
        for (int j = 0; j < 4; j++)
            Cpart[(size_t)(z * 64 + tx * 4 + j) * M + m0 + ty * 4 + i] = acc[i][j];
}

// Variant with indexed activation rows: act row n = emb[idx[n]] (embedding).
__device__ __forceinline__ void splitk_body_idx(
    const float* __restrict__ A, int lda,
    const float* __restrict__ emb, const int* __restrict__ idx,
    float* __restrict__ Cpart, int M, int Ks, int m0, int z)
{
    __shared__ float As[16][68];
    __shared__ float Bs[16][68];
    const int tid = threadIdx.x;

    const int lrow = tid >> 2, lk = (tid & 3) * 4;
    const float* Ap = A + (size_t)(m0 + lrow) * lda + z * Ks + lk;
    const float* Bp = emb + (size_t)idx[lrow] * Hc + z * Ks + lk;

    const int ty = tid >> 4, tx = tid & 15;
    float acc[4][4] = {};

    for (int k0 = 0; k0 < Ks; k0 += 16) {
        float4 av = *(const float4*)(Ap + k0);
        float4 bv = *(const float4*)(Bp + k0);
        As[lk + 0][lrow] = av.x; As[lk + 1][lrow] = av.y;
        As[lk + 2][lrow] = av.z; As[lk + 3][lrow] = av.w;
        Bs[lk + 0][lrow] = bv.x; Bs[lk + 1][lrow] = bv.y;
        Bs[lk + 2][lrow] = bv.z; Bs[lk + 3][lrow] = bv.w;
        __syncthreads();
#pragma unroll
        for (int k = 0; k < 16; k++) {
            float4 a = *(const float4*)&As[k][ty * 4];
            float4 b = *(const float4*)&Bs[k][tx * 4];
            float ar[4] = {a.x, a.y, a.z, a.w};
            float br[4] = {b.x, b.y, b.z, b.w};
#pragma unroll
            for (int i = 0; i < 4; i++)
#pragma unroll
                for (int j = 0; j < 4; j++)
                    acc[i][j] += ar[i] * br[j];
        }
        __syncthreads();
    }

#pragma unroll
    for (int i = 0; i < 4; i++)
#pragma unroll
        for (int j = 0; j < 4; j++)
            Cpart[(size_t)(z * 64 + tx * 4 + j) * M + m0 + ty * 4 + i] = acc[i][j];
}

// Pre-attention launch: hWh partials (16) + gh partials (48) + gi-emb (48).
__global__ void __launch_bounds__(256)
splitk_pre(const float* __restrict__ attn_w_W, const float* __restrict__ hidden,
           const float* __restrict__ gru_Whh, const float* __restrict__ gru_Wih,
           const float* __restrict__ emb, const int* __restrict__ input,
           float* __restrict__ hWhp, float* __restrict__ ghp, float* __restrict__ gip)
{
    const int bx = blockIdx.x, z = blockIdx.z;
    if (bx < 16)
        splitk_body(attn_w_W, 2 * Hc, hidden, Hc, hWhp, Hc, 256, bx * 64, z);
    else if (bx < 64)
        splitk_body(gru_Whh, Hc, hidden, Hc, ghp, 3 * Hc, 256, (bx - 16) * 64, z);
    else
        splitk_body_idx(gru_Wih, 2 * Hc, emb, input, gip, 3 * Hc, 256, (bx - 64) * 64, z);
}

// gi ctx-half partials (post-context): Wih columns [H:2H) @ ctx.
__global__ void __launch_bounds__(256)
splitk_gictx(const float* __restrict__ gru_Wih, const float* __restrict__ ctx,
             float* __restrict__ gip_hi)
{
    splitk_body(gru_Wih + Hc, 2 * Hc, ctx, Hc, gip_hi, 3 * Hc, 256,
                blockIdx.x * 64, blockIdx.z);
}

// ===========================================================================
// Logits GEMM: 2-term split-tf32, 3-stage K=32 pipeline. [R10 proven]
// ===========================================================================
#define LG_SMEM 82944

__global__ void __launch_bounds__(256, 2)
gemm_wact_tc(const float* __restrict__ A, int lda,
             const float* __restrict__ act,
             float* __restrict__ C, int ldc,
             const float* __restrict__ bias)
{
    extern __shared__ float sm[];
    const int tid = threadIdx.x, lane = tid & 31, wid = tid >> 5;
    const int m0 = blockIdx.x * 128;
    const int wm = (wid & 3) * 32, wn = (wid >> 2) * 32;
    const uint32_t sbase = smem_u32(sm);
    const int fr = lane >> 2, fc = lane & 3;

    float acc[2][4][4] = {};

#define LG_LOAD(buf, kk)                                                      \
    do {                                                                      \
        const uint32_t db = sbase + (buf) * 27648u;                           \
        _Pragma("unroll")                                                     \
        for (int i_ = 0; i_ < 4; i_++) {                                      \
            int c_ = i_ * 256 + tid;                                          \
            int row_ = c_ >> 3, kc_ = c_ & 7;                                 \
            CPA(db + (row_ * 36 + kc_ * 4) * 4,                               \
                A + (size_t)(m0 + row_) * lda + (kk) + kc_ * 4);              \
        }                                                                     \
        _Pragma("unroll")                                                     \
        for (int i_ = 0; i_ < 2; i_++) {                                      \
            int c_ = i_ * 256 + tid;                                          \
            int row_ = c_ >> 3, kc_ = c_ & 7;                                 \
            CPA(db + 18432u + (row_ * 36 + kc_ * 4) * 4,                      \
                act + (size_t)row_ * Hc + (kk) + kc_ * 4);                    \
        }                                                                     \
        CPCOMMIT();                                                           \
    } while (0)

#define LG_STEP(ks, buf)                                                      \
    do {                                                                      \
        CPWAIT(1);                                                            \
        __syncthreads();                                                      \
        if ((ks) + 2 < 32) LG_LOAD(((ks) + 2) % 3, ((ks) + 2) * 32);          \
        else               CPCOMMIT();                                        \
        const float* Sa = sm + (buf) * 6912;                                  \
        const float* Sb = Sa + 4608;                                          \
        _Pragma("unroll")                                                     \
        for (int kh = 0; kh < 4; kh++) {                                      \
            const int k8 = kh * 8;                                            \
            uint32_t a[2][4], bh[4][2], bl[4][2];                             \
            _Pragma("unroll")                                                 \
            for (int mi = 0; mi < 2; mi++) {                                  \
                const float* ap = Sa + (wm + 16 * mi + fr) * 36 + k8 + fc;    \
                a[mi][0] = __float_as_uint(ap[0]);                            \
                a[mi][1] = __float_as_uint(ap[288]);                          \
                a[mi][2] = __float_as_uint(ap[4]);                            \
                a[mi][3] = __float_as_uint(ap[292]);                          \
            }                                                                 \
            _Pragma("unroll")                                                 \
            for (int nj = 0; nj < 4; nj++) {                                  \
                const float* bp = Sb + (wn + 8 * nj + fr) * 36 + k8 + fc;     \
                split_tf32(bp[0], bh[nj][0], bl[nj][0]);                      \
                split_tf32(bp[4], bh[nj][1], bl[nj][1]);                      \
            }                                                                 \
            _Pragma("unroll")                                                 \
            for (int mi = 0; mi < 2; mi++)                                    \
                _Pragma("unroll")                                             \
                for (int nj = 0; nj < 4; nj++) {                              \
                    mma_tf32(acc[mi][nj], a[mi], bl[nj]);                     \
                    mma_tf32(acc[mi][nj], a[mi], bh[nj]);                     \
                }                                                             \
        }                                                                     \
    } while (0)

    LG_LOAD(0, 0);
    LG_LOAD(1, 32);

    for (int ks = 0; ks < 30; ks += 3) {
        LG_STEP(ks + 0, 0);
        LG_STEP(ks + 1, 1);
        LG_STEP(ks + 2, 2);
    }
    LG_STEP(30, 0);
    LG_STEP(31, 1);
#undef LG_STEP
#undef LG_LOAD

    const int c2 = (lane & 3) * 2;
#pragma unroll
    for (int mi = 0; mi < 2; mi++) {
        const int m = m0 + wm + 16 * mi + fr;
        const float bm0 = bias[m], bm1 = bias[m + 8];
#pragma unroll
        for (int nj = 0; nj < 4; nj++) {
            const int n = wn + 8 * nj + c2;
            C[(size_t)n * ldc + m]           = acc[mi][nj][0] + bm0;
            C[(size_t)(n + 1) * ldc + m]     = acc[mi][nj][1] + bm0;
            C[(size_t)n * ldc + m + 8]       = acc[mi][nj][2] + bm1;
            C[(size_t)(n + 1) * ldc + m + 8] = acc[mi][nj][3] + bm1;
        }
    }
}

// ===========================================================================
// Softmax over seq (512) per batch; writes attn_weights (output region 3).
// ===========================================================================
__global__ void __launch_bounds__(256)
softmax_kernel(float* __restrict__ wout)
{
    __shared__ float sc[Sc];
    __shared__ float red[256];
    const int b = blockIdx.x, tid = threadIdx.x;

    for (int s = tid; s < Sc; s += 256) {
        const float4* p = (const float4*)&g_spart[(size_t)(s * Bc + b) * 16];
        float v = 0.0f;
#pragma unroll
        for (int i = 0; i < 4; i++) {
            float4 q = p[i];
            v += q.x + q.y + q.z + q.w;
        }
        sc[s] = v;
    }
    __syncthreads();

    float m = fmaxf(sc[tid], sc[tid + 256]);
    red[tid] = m;
    __syncthreads();
    for (int st = 128; st > 0; st >>= 1) {
        if (tid < st) red[tid] = fmaxf(red[tid], red[tid + st]);
        __syncthreads();
    }
    float mx = red[0];
    __syncthreads();

    float e0 = expf(sc[tid] - mx);
    float e1 = expf(sc[tid + 256] - mx);
    red[tid] = e0 + e1;
    __syncthreads();
    for (int st = 128; st > 0; st >>= 1) {
        if (tid < st) red[tid] += red[tid + st];
        __syncthreads();
    }
    float inv = 1.0f / red[0];

    wout[(size_t)tid * Bc + b]         = e0 * inv;
    wout[(size_t)(tid + 256) * Bc + b] = e1 * inv;
}

// ===========================================================================
// Context. grid (16 k-chunks, 64 b), 256 threads -> g_ctx[b][h].
// ===========================================================================
__global__ void __launch_bounds__(256)
ctx_kernel(const float* __restrict__ enc, const float* __restrict__ wts)
{
    __shared__ float w[Sc];
    __shared__ float part[4][64];
    const int kc = blockIdx.x, b = blockIdx.y, tid = threadIdx.x;

    w[tid]       = wts[(size_t)tid * Bc + b];
    w[tid + 256] = wts[(size_t)(tid + 256) * Bc + b];
    __syncthreads();

    const int kk = tid & 63, sg = tid >> 6;
    const int k = kc * 64 + kk;

    const float* p = enc + ((size_t)(sg * 128) * Bc + b) * Hc + k;
    const float* wp = w + sg * 128;
    float acc = 0.0f;
#pragma unroll 8
    for (int s = 0; s < 128; s++)
        acc += wp[s] * p[(size_t)s * (Bc * Hc)];
    part[sg][kk] = acc;
    __syncthreads();

    if (tid < 64)
        g_ctx[(size_t)b * Hc + kc * 64 + tid] =
            (part[0][tid] + part[1][tid]) + (part[2][tid] + part[3][tid]);
}

// GRU gate combine: sums 8 gi partials (emb+ctx) and 4 gh partials (exact fp32).
__global__ void __launch_bounds__(256)
gru_kernel(const float* __restrict__ hidden, float* __restrict__ hnew,
           const float* __restrict__ bih, const float* __restrict__ bhh)
{
    const int g = blockIdx.x * 256 + threadIdx.x;   // 65536
    const int b = g >> 10, h = g & 1023;

    float gir = bih[h],            ghr = bhh[h];
    float giz = bih[Hc + h],       ghz = bhh[Hc + h];
    float gin = bih[2 * Hc + h],   ghn = bhh[2 * Hc + h];
#pragma unroll
    for (int z = 0; z < 8; z++) {
        const float* gi = g_gip + (size_t)(z * 64 + b) * (3 * Hc);
        gir += gi[h];
        giz += gi[Hc + h];
        gin += gi[2 * Hc + h];
    }
#pragma unroll
    for (int z = 0; z < 4; z++) {
        const float* gh = g_ghp + (size_t)(z * 64 + b) * (3 * Hc);
        ghr += gh[h];
        ghz += gh[Hc + h];
        ghn += gh[2 * Hc + h];
    }
    float r = 1.0f / (1.0f + expf(-(gir + ghr)));
    float z = 1.0f / (1.0f + expf(-(giz + ghz)));
    float n = tanhf(gin + r * ghn);
    float hp = hidden[g];
    hnew[g] = (1.0f - z) * n + z * hp;
}

// ===========================================================================
extern "C" void kernel_launch(void* const* d_in, const int* in_sizes, int n_in,
                              void* d_out, int out_size)
{
    const int*   input    = (const int*)d_in[0];
    const float* hidden   = (const float*)d_in[1];
    const float* enc      = (const float*)d_in[2];
    const float* emb      = (const float*)d_in[3];
    const float* attn_w_W = (const float*)d_in[4];
    const float* attn_w_b = (const float*)d_in[5];
    const float* attn_v_W = (const float*)d_in[6];
    // d_in[7] = attn_v_b : softmax-invariant, skipped
    const float* gru_Wih  = (const float*)d_in[8];
    const float* gru_Whh  = (const float*)d_in[9];
    const float* gru_bih  = (const float*)d_in[10];
    const float* gru_bhh  = (const float*)d_in[11];
    const float* out_W    = (const float*)d_in[12];
    const float* out_b    = (const float*)d_in[13];

    float* out    = (float*)d_out;
    float* logits = out;                        // B*V
    float* hnew   = out + (size_t)Bc * Vc;      // B*H
    float* wts    = hnew + (size_t)Bc * Hc;     // S*B

    float *p_hWhp, *p_ctx, *p_gip, *p_ghp;
    cudaGetSymbolAddress((void**)&p_hWhp, g_hWhp);
    cudaGetSymbolAddress((void**)&p_ctx,  g_ctx);
    cudaGetSymbolAddress((void**)&p_gip,  g_gip);
    cudaGetSymbolAddress((void**)&p_ghp,  g_ghp);

    cudaFuncSetAttribute(attn_score_tc, cudaFuncAttributeMaxDynamicSharedMemorySize, ATT_SMEM);
    cudaFuncSetAttribute(gemm_wact_tc,  cudaFuncAttributeMaxDynamicSharedMemorySize, LG_SMEM);

    // 1. hWh partials + gh partials + gi emb-half partials (exact fp32)
    splitk_pre<<<dim3(112, 1, 4), 256>>>(attn_w_W, hidden, gru_Whh, gru_Wih,
                                         emb, input, p_hWhp, p_ghp, p_gip);
    // 2. fused attention scores (epilogue sums hWh partials + bias directly)
    attn_score_tc<<<dim3(8, 256), 128, ATT_SMEM>>>(enc, attn_w_W, attn_v_W, attn_w_b);
    // 3. softmax -> attn_weights (output region 3)
    softmax_kernel<<<Bc, 256>>>(wts);
    // 4. context (1024 CTAs) -> g_ctx
    ctx_kernel<<<dim3(16, Bc), 256>>>(enc, wts);
    // 5. gi ctx-half partials (exact fp32, K halved)
    splitk_gictx<<<dim3(48, 1, 4), 256>>>(gru_Wih, p_ctx,
                                          p_gip + (size_t)4 * 64 * 3 * Hc);
    // 6. GRU combine -> h_new (output region 2)
    gru_kernel<<<Bc * Hc / 256, 256>>>(hidden, hnew, gru_bih, gru_bhh);
    // 7. logits = h_new @ out_W^T + out_b (2-term split-tf32, output region 1)
    gemm_wact_tc<<<Vc / 128, 256, LG_SMEM>>>(out_W, Hc, hnew, logits, Vc, out_b);
}

// round 12
// speedup vs baseline: 1.4728x; 1.1605x over previous
#include <cuda_runtime.h>
#include <cuda_bf16.h>
#include <cstdint>
#include <cstddef>

#define Bc 64
#define Sc 512
#define Hc 1024
#define Vc 32000
#define SB (Sc * Bc)

// ---------------- scratch (device globals, no allocation) ----------------
__device__ float g_hWhp[4 * Bc * Hc];    // hWh split-K partials [z][b][h]
__device__ float g_spart[SB * 16];       // 16 partial scores per row r = s*B+b
__device__ float g_ctx[Bc * Hc];         // context [b][h]
__device__ float g_gip[8 * Bc * 3 * Hc]; // gi partials: z0-3 emb-half, z4-7 ctx-half
__device__ float g_ghp[4 * Bc * 3 * Hc]; // gh split-K partials [z][b][3H]
__device__ __nv_bfloat16 g_encb[(size_t)SB * Hc];  // enc in bf16 (64MB)
__device__ __nv_bfloat16 g_wb[Hc * Hc];            // We = attn_w_W[:,H:2H] bf16

// ---------------- portable-PTX helpers ----------------
__device__ __forceinline__ uint32_t smem_u32(const void* p) {
    uint32_t a;
    asm("{ .reg .u64 t; cvta.to.shared.u64 t, %1; cvt.u32.u64 %0, t; }"
        : "=r"(a) : "l"(p));
    return a;
}
#define CPA(dst, src) \
    asm volatile("cp.async.cg.shared.global [%0], [%1], 16;" :: "r"(dst), "l"(src))
#define CPCOMMIT() asm volatile("cp.async.commit_group;" ::: "memory")
#define CPWAIT(n)  asm volatile("cp.async.wait_group %0;" :: "n"(n) : "memory")

__device__ __forceinline__ void mma_tf32(float* c, const uint32_t* a, const uint32_t* b) {
    asm volatile(
        "mma.sync.aligned.m16n8k8.row.col.f32.tf32.tf32.f32 "
        "{%0,%1,%2,%3}, {%4,%5,%6,%7}, {%8,%9}, {%0,%1,%2,%3};"
        : "+f"(c[0]), "+f"(c[1]), "+f"(c[2]), "+f"(c[3])
        : "r"(a[0]), "r"(a[1]), "r"(a[2]), "r"(a[3]), "r"(b[0]), "r"(b[1]));
}
__device__ __forceinline__ void mma_bf16(float* c, const uint32_t* a, const uint32_t* b) {
    asm volatile(
        "mma.sync.aligned.m16n8k16.row.col.f32.bf16.bf16.f32 "
        "{%0,%1,%2,%3}, {%4,%5,%6,%7}, {%8,%9}, {%0,%1,%2,%3};"
        : "+f"(c[0]), "+f"(c[1]), "+f"(c[2]), "+f"(c[3])
        : "r"(a[0]), "r"(a[1]), "r"(a[2]), "r"(a[3]), "r"(b[0]), "r"(b[1]));
}
__device__ __forceinline__ void split_tf32(float x, uint32_t& hi, uint32_t& lo) {
    uint32_t h = __float_as_uint(x) & 0xFFFFE000u;
    hi = h;
    lo = __float_as_uint(x - __uint_as_float(h));   // exact (same exponent)
}
__device__ __forceinline__ uint32_t pack_bf(float a, float b) {
    __nv_bfloat162 t = __floats2bfloat162_rn(a, b);
    return *(uint32_t*)&t;
}

// ===========================================================================
// Convert enc (fp32 -> bf16) and We slice (attn_w_W[:,H:2H] -> bf16).
// grid: 33792 blocks x 256 threads; first 8388608 float4 = enc, rest = W.
// ===========================================================================
__global__ void __launch_bounds__(256)
convert_bf16(const float* __restrict__ enc, const float* __restrict__ W)
{
    const size_t i = (size_t)blockIdx.x * 256 + threadIdx.x;
    if (i < 8388608) {
        float4 v = ((const float4*)enc)[i];
        uint2 o = {pack_bf(v.x, v.y), pack_bf(v.z, v.w)};
        ((uint2*)g_encb)[i] = o;
    } else {
        const size_t j = i - 8388608;            // 262144 float4 for W
        const int r = (int)(j >> 8);             // 256 float4 per 1024-col row
        const int c = ((int)j & 255) * 4;
        float4 v = *(const float4*)(W + (size_t)r * 2048 + Hc + c);
        uint2 o = {pack_bf(v.x, v.y), pack_bf(v.z, v.w)};
        ((uint2*)g_wb)[j] = o;
    }
}

// ===========================================================================
// Attention score kernel (mma.sync BF16 m16n8k16). CTA tile 128x128, FOUR
// warps of 64x64 (128 threads). 3-stage K=32 pipeline, static buffers via
// manual unroll-by-3, ONE sync/iter. 3 CTAs/SM (stage 20KB).
// Row stride 80B (40 halves) -> conflict-free fragment loads.
// Epilogue (fp32, unchanged): sums 4 hWh partials + bias, tanh*v reduce.
// ===========================================================================
#define ATT_SMEM 61440   // 3 stages x 20480

__global__ void __launch_bounds__(128, 3)
attn_score_tc(const float* __restrict__ vvec, const float* __restrict__ awb)
{
    extern __shared__ char smb[];
    float* smf = (float*)smb;
    const int tid = threadIdx.x, lane = tid & 31, wid = tid >> 5;
    const int n0 = blockIdx.x * 128, m0 = blockIdx.y * 128;
    const int wm = (wid >> 1) * 64, wn = (wid & 1) * 64;
    const uint32_t sbase = smem_u32(smb);
    const int fr = lane >> 2, fc = lane & 3;

    float acc[4][8][4] = {};

#define LOAD_STAGE(buf, kk)                                                   \
    do {                                                                      \
        const uint32_t db = sbase + (buf) * 20480u;                           \
        _Pragma("unroll")                                                     \
        for (int i_ = 0; i_ < 4; i_++) {                                      \
            int c_ = i_ * 128 + tid;                                          \
            int row_ = c_ >> 2, kc_ = c_ & 3;                                 \
            CPA(db + (uint32_t)(row_ * 80 + kc_ * 16),                        \
                g_encb + (size_t)(m0 + row_) * Hc + (kk) + kc_ * 8);          \
            CPA(db + 10240u + (uint32_t)(row_ * 80 + kc_ * 16),               \
                g_wb + (size_t)(n0 + row_) * Hc + (kk) + kc_ * 8);            \
        }                                                                     \
        CPCOMMIT();                                                           \
    } while (0)

#define STEP(ks, buf)                                                         \
    do {                                                                      \
        CPWAIT(1);                                                            \
        __syncthreads();                                                      \
        if ((ks) + 2 < 32) LOAD_STAGE(((ks) + 2) % 3, ((ks) + 2) * 32);       \
        else               CPCOMMIT();                                        \
        const char* Sa = smb + (buf) * 20480;                                 \
        const char* Sb = Sa + 10240;                                          \
        _Pragma("unroll")                                                     \
        for (int kh = 0; kh < 2; kh++) {                                      \
            const int koff = kh * 32;                                         \
            uint32_t a[4][4], b[8][2];                                        \
            _Pragma("unroll")                                                 \
            for (int mi = 0; mi < 4; mi++) {                                  \
                const char* ap = Sa + (wm + 16 * mi + fr) * 80 + koff + fc * 4; \
                a[mi][0] = *(const uint32_t*)(ap);                            \
                a[mi][1] = *(const uint32_t*)(ap + 640);                      \
                a[mi][2] = *(const uint32_t*)(ap + 16);                       \
                a[mi][3] = *(const uint32_t*)(ap + 656);                      \
            }                                                                 \
            _Pragma("unroll")                                                 \
            for (int nj = 0; nj < 8; nj++) {                                  \
                const char* bp = Sb + (wn + 8 * nj + fr) * 80 + koff + fc * 4; \
                b[nj][0] = *(const uint32_t*)(bp);                            \
                b[nj][1] = *(const uint32_t*)(bp + 16);                       \
            }                                                                 \
            _Pragma("unroll")                                                 \
            for (int mi = 0; mi < 4; mi++)                                    \
                _Pragma("unroll")                                             \
                for (int nj = 0; nj < 8; nj++)                                \
                    mma_bf16(acc[mi][nj], a[mi], b[nj]);                      \
        }                                                                     \
    } while (0)

    LOAD_STAGE(0, 0);
    LOAD_STAGE(1, 32);

    for (int ks = 0; ks < 30; ks += 3) {
        STEP(ks + 0, 0);
        STEP(ks + 1, 1);
        STEP(ks + 2, 2);
    }
    STEP(30, 0);
    STEP(31, 1);
#undef STEP
#undef LOAD_STAGE
    __syncthreads();

    // ---- epilogue: stage (bias + sum of 4 hWh partials), stride 133 ----
    float* shf = smf;
    float* shv = smf + 64 * 133;
    for (int j = tid; j < 2048; j += 128) {      // 2048 float4 = 64x128 floats
        int row = j >> 5, seg = j & 31;
        float4 v = *(const float4*)(awb + n0 + seg * 4);
#pragma unroll
        for (int z = 0; z < 4; z++) {
            float4 p = *(const float4*)(g_hWhp + (size_t)(z * 64 + row) * Hc + n0 + seg * 4);
            v.x += p.x; v.y += p.y; v.z += p.z; v.w += p.w;
        }
        float* d = &shf[row * 133 + seg * 4];
        d[0] = v.x; d[1] = v.y; d[2] = v.z; d[3] = v.w;
    }
    shv[tid] = vvec[n0 + tid];
    __syncthreads();

    const int c2 = (lane & 3) * 2;
    float s[4][2] = {};
#pragma unroll
    for (int mi = 0; mi < 4; mi++) {
        const int R0 = wm + 16 * mi + fr;
        const int b0 = R0 & 63, b1 = (R0 + 8) & 63;
#pragma unroll
        for (int nj = 0; nj < 8; nj++) {
            const int n = wn + 8 * nj + c2;
            const float v0 = shv[n], v1 = shv[n + 1];
            s[mi][0] += tanhf(acc[mi][nj][0] + shf[b0 * 133 + n]) * v0
                      + tanhf(acc[mi][nj][1] + shf[b0 * 133 + n + 1]) * v1;
            s[mi][1] += tanhf(acc[mi][nj][2] + shf[b1 * 133 + n]) * v0
                      + tanhf(acc[mi][nj][3] + shf[b1 * 133 + n + 1]) * v1;
        }
    }
#pragma unroll
    for (int mi = 0; mi < 4; mi++)
#pragma unroll
        for (int h = 0; h < 2; h++) {
            s[mi][h] += __shfl_xor_sync(0xffffffffu, s[mi][h], 1);
            s[mi][h] += __shfl_xor_sync(0xffffffffu, s[mi][h], 2);
        }
    if ((lane & 3) == 0) {
        const int col = blockIdx.x * 2 + (wid & 1);
#pragma unroll
        for (int mi = 0; mi < 4; mi++) {
            const int R0 = wm + 16 * mi + fr;
            g_spart[(size_t)(m0 + R0) * 16 + col]     = s[mi][0];
            g_spart[(size_t)(m0 + R0 + 8) * 16 + col] = s[mi][1];
        }
    }
}

// ===========================================================================
// Exact fp32 SIMT split-K GEMM bodies.
// ===========================================================================
__device__ __forceinline__ void splitk_body(
    const float* __restrict__ A, int lda,
    const float* __restrict__ act, int ldact,
    float* __restrict__ Cpart, int M, int Ks, int m0, int z)
{
    __shared__ float As[16][68];
    __shared__ float Bs[16][68];
    const int tid = threadIdx.x;

    const int lrow = tid >> 2, lk = (tid & 3) * 4;
    const float* Ap = A + (size_t)(m0 + lrow) * lda + z * Ks + lk;
    const float* Bp = act + (size_t)lrow * ldact + z * Ks + lk;

    const int ty = tid >> 4, tx = tid & 15;
    float acc[4][4] = {};

    for (int k0 = 0; k0 < Ks; k0 += 16) {
        float4 av = *(const float4*)(Ap + k0);
        float4 bv = *(const float4*)(Bp + k0);
        As[lk + 0][lrow] = av.x; As[lk + 1][lrow] = av.y;
        As[lk + 2][lrow] = av.z; As[lk + 3][lrow] = av.w;
        Bs[lk + 0][lrow] = bv.x; Bs[lk + 1][lrow] = bv.y;
        Bs[lk + 2][lrow] = bv.z; Bs[lk + 3][lrow] = bv.w;
        __syncthreads();
#pragma unroll
        for (int k = 0; k < 16; k++) {
            float4 a = *(const float4*)&As[k][ty * 4];
            float4 b = *(const float4*)&Bs[k][tx * 4];
            float ar[4] = {a.x, a.y, a.z, a.w};
            float br[4] = {b.x, b.y, b.z, b.w};
#pragma unroll
            for (int i = 0; i < 4; i++)
#pragma unroll
                for (int j = 0; j < 4; j++)
                    acc[i][j] += ar[i] * br[j];
        }
        __syncthreads();
    }

#pragma unroll
    for (int i = 0; i < 4; i++)
#pragma unroll
        for (int j = 0; j < 4; j++)
            Cpart[(size_t)(z * 64 + tx * 4 + j) * M + m0 + ty * 4 + i] = acc[i][j];
}

// Variant with indexed activation rows: act row n = emb[idx[n]] (embedding).
__device__ __forceinline__ void splitk_body_idx(
    const float* __restrict__ A, int lda,
    const float* __restrict__ emb, const int* __restrict__ idx,
    float* __restrict__ Cpart, int M, int Ks, int m0, int z)
{
    __shared__ float As[16][68];
    __shared__ float Bs[16][68];
    const int tid = threadIdx.x;

    const int lrow = tid >> 2, lk = (tid & 3) * 4;
    const float* Ap = A + (size_t)(m0 + lrow) * lda + z * Ks + lk;
    const float* Bp = emb + (size_t)idx[lrow] * Hc + z * Ks + lk;

    const int ty = tid >> 4, tx = tid & 15;
    float acc[4][4] = {};

    for (int k0 = 0; k0 < Ks; k0 += 16) {
        float4 av = *(const float4*)(Ap + k0);
        float4 bv = *(const float4*)(Bp + k0);
        As[lk + 0][lrow] = av.x; As[lk + 1][lrow] = av.y;
        As[lk + 2][lrow] = av.z; As[lk + 3][lrow] = av.w;
        Bs[lk + 0][lrow] = bv.x; Bs[lk + 1][lrow] = bv.y;
        Bs[lk + 2][lrow] = bv.z; Bs[lk + 3][lrow] = bv.w;
        __syncthreads();
#pragma unroll
        for (int k = 0; k < 16; k++) {
            float4 a = *(const float4*)&As[k][ty * 4];
            float4 b = *(const float4*)&Bs[k][tx * 4];
            float ar[4] = {a.x, a.y, a.z, a.w};
            float br[4] = {b.x, b.y, b.z, b.w};
#pragma unroll
            for (int i = 0; i < 4; i++)
#pragma unroll
                for (int j = 0; j < 4; j++)
                    acc[i][j] += ar[i] * br[j];
        }
        __syncthreads();
    }

#pragma unroll
    for (int i = 0; i < 4; i++)
#pragma unroll
        for (int j = 0; j < 4; j++)
            Cpart[(size_t)(z * 64 + tx * 4 + j) * M + m0 + ty * 4 + i] = acc[i][j];
}

// Pre-attention launch: hWh partials (16) + gh partials (48) + gi-emb (48).
__global__ void __launch_bounds__(256)
splitk_pre(const float* __restrict__ attn_w_W, const float* __restrict__ hidden,
           const float* __restrict__ gru_Whh, const float* __restrict__ gru_Wih,
           const float* __restrict__ emb, const int* __restrict__ input,
           float* __restrict__ hWhp, float* __restrict__ ghp, float* __restrict__ gip)
{
    const int bx = blockIdx.x, z = blockIdx.z;
    if (bx < 16)
        splitk_body(attn_w_W, 2 * Hc, hidden, Hc, hWhp, Hc, 256, bx * 64, z);
    else if (bx < 64)
        splitk_body(gru_Whh, Hc, hidden, Hc, ghp, 3 * Hc, 256, (bx - 16) * 64, z);
    else
        splitk_body_idx(gru_Wih, 2 * Hc, emb, input, gip, 3 * Hc, 256, (bx - 64) * 64, z);
}

// gi ctx-half partials (post-context): Wih columns [H:2H) @ ctx.
__global__ void __launch_bounds__(256)
splitk_gictx(const float* __restrict__ gru_Wih, const float* __restrict__ ctx,
             float* __restrict__ gip_hi)
{
    splitk_body(gru_Wih + Hc, 2 * Hc, ctx, Hc, gip_hi, 3 * Hc, 256,
                blockIdx.x * 64, blockIdx.z);
}

// ===========================================================================
// Logits GEMM: 2-term split-tf32, 3-stage K=32 pipeline. [R10 proven]
// ===========================================================================
#define LG_SMEM 82944

__global__ void __launch_bounds__(256, 2)
gemm_wact_tc(const float* __restrict__ A, int lda,
             const float* __restrict__ act,
             float* __restrict__ C, int ldc,
             const float* __restrict__ bias)
{
    extern __shared__ float sm[];
    const int tid = threadIdx.x, lane = tid & 31, wid = tid >> 5;
    const int m0 = blockIdx.x * 128;
    const int wm = (wid & 3) * 32, wn = (wid >> 2) * 32;
    const uint32_t sbase = smem_u32(sm);
    const int fr = lane >> 2, fc = lane & 3;

    float acc[2][4][4] = {};

#define LG_LOAD(buf, kk)                                                      \
    do {                                                                      \
        const uint32_t db = sbase + (buf) * 27648u;                           \
        _Pragma("unroll")                                                     \
        for (int i_ = 0; i_ < 4; i_++) {                                      \
            int c_ = i_ * 256 + tid;                                          \
            int row_ = c_ >> 3, kc_ = c_ & 7;                                 \
            CPA(db + (row_ * 36 + kc_ * 4) * 4,                               \
                A + (size_t)(m0 + row_) * lda + (kk) + kc_ * 4);              \
        }                                                                     \
        _Pragma("unroll")                                                     \
        for (int i_ = 0; i_ < 2; i_++) {                                      \
            int c_ = i_ * 256 + tid;                                          \
            int row_ = c_ >> 3, kc_ = c_ & 7;                                 \
            CPA(db + 18432u + (row_ * 36 + kc_ * 4) * 4,                      \
                act + (size_t)row_ * Hc + (kk) + kc_ * 4);                    \
        }                                                                     \
        CPCOMMIT();                                                           \
    } while (0)

#define LG_STEP(ks, buf)                                                      \
    do {                                                                      \
        CPWAIT(1);                                                            \
        __syncthreads();                                                      \
        if ((ks) + 2 < 32) LG_LOAD(((ks) + 2) % 3, ((ks) + 2) * 32);          \
        else               CPCOMMIT();                                        \
        const float* Sa = sm + (buf) * 6912;                                  \
        const float* Sb = Sa + 4608;                                          \
        _Pragma("unroll")                                                     \
        for (int kh = 0; kh < 4; kh++) {                                      \
            const int k8 = kh * 8;                                            \
            uint32_t a[2][4], bh[4][2], bl[4][2];                             \
            _Pragma("unroll")                                                 \
            for (int mi = 0; mi < 2; mi++) {                                  \
                const float* ap = Sa + (wm + 16 * mi + fr) * 36 + k8 + fc;    \
                a[mi][0] = __float_as_uint(ap[0]);                            \
                a[mi][1] = __float_as_uint(ap[288]);                          \
                a[mi][2] = __float_as_uint(ap[4]);                            \
                a[mi][3] = __float_as_uint(ap[292]);                          \
            }                                                                 \
            _Pragma("unroll")                                                 \
            for (int nj = 0; nj < 4; nj++) {                                  \
                const float* bp = Sb + (wn + 8 * nj + fr) * 36 + k8 + fc;     \
                split_tf32(bp[0], bh[nj][0], bl[nj][0]);                      \
                split_tf32(bp[4], bh[nj][1], bl[nj][1]);                      \
            }                                                                 \
            _Pragma("unroll")                                                 \
            for (int mi = 0; mi < 2; mi++)                                    \
                _Pragma("unroll")                                             \
                for (int nj = 0; nj < 4; nj++) {                              \
                    mma_tf32(acc[mi][nj], a[mi], bl[nj]);                     \
                    mma_tf32(acc[mi][nj], a[mi], bh[nj]);                     \
                }                                                             \
        }                                                                     \
    } while (0)

    LG_LOAD(0, 0);
    LG_LOAD(1, 32);

    for (int ks = 0; ks < 30; ks += 3) {
        LG_STEP(ks + 0, 0);
        LG_STEP(ks + 1, 1);
        LG_STEP(ks + 2, 2);
    }
    LG_STEP(30, 0);
    LG_STEP(31, 1);
#undef LG_STEP
#undef LG_LOAD

    const int c2 = (lane & 3) * 2;
#pragma unroll
    for (int mi = 0; mi < 2; mi++) {
        const int m = m0 + wm + 16 * mi + fr;
        const float bm0 = bias[m], bm1 = bias[m + 8];
#pragma unroll
        for (int nj = 0; nj < 4; nj++) {
            const int n = wn + 8 * nj + c2;
            C[(size_t)n * ldc + m]           = acc[mi][nj][0] + bm0;
            C[(size_t)(n + 1) * ldc + m]     = acc[mi][nj][1] + bm0;
            C[(size_t)n * ldc + m + 8]       = acc[mi][nj][2] + bm1;
            C[(size_t)(n + 1) * ldc + m + 8] = acc[mi][nj][3] + bm1;
        }
    }
}

// ===========================================================================
// Softmax over seq (512) per batch; writes attn_weights (output region 3).
// ===========================================================================
__global__ void __launch_bounds__(256)
softmax_kernel(float* __restrict__ wout)
{
    __shared__ float sc[Sc];
    __shared__ float red[256];
    const int b = blockIdx.x, tid = threadIdx.x;

    for (int s = tid; s < Sc; s += 256) {
        const float4* p = (const float4*)&g_spart[(size_t)(s * Bc + b) * 16];
        float v = 0.0f;
#pragma unroll
        for (int i = 0; i < 4; i++) {
            float4 q = p[i];
            v += q.x + q.y + q.z + q.w;
        }
        sc[s] = v;
    }
    __syncthreads();

    float m = fmaxf(sc[tid], sc[tid + 256]);
    red[tid] = m;
    __syncthreads();
    for (int st = 128; st > 0; st >>= 1) {
        if (tid < st) red[tid] = fmaxf(red[tid], red[tid + st]);
        __syncthreads();
    }
    float mx = red[0];
    __syncthreads();

    float e0 = expf(sc[tid] - mx);
    float e1 = expf(sc[tid + 256] - mx);
    red[tid] = e0 + e1;
    __syncthreads();
    for (int st = 128; st > 0; st >>= 1) {
        if (tid < st) red[tid] += red[tid + st];
        __syncthreads();
    }
    float inv = 1.0f / red[0];

    wout[(size_t)tid * Bc + b]         = e0 * inv;
    wout[(size_t)(tid + 256) * Bc + b] = e1 * inv;
}

// ===========================================================================
// Context. grid (16 k-chunks, 64 b), 256 threads -> g_ctx[b][h].
// ===========================================================================
__global__ void __launch_bounds__(256)
ctx_kernel(const float* __restrict__ enc, const float* __restrict__ wts)
{
    __shared__ float w[Sc];
    __shared__ float part[4][64];
    const int kc = blockIdx.x, b = blockIdx.y, tid = threadIdx.x;

    w[tid]       = wts[(size_t)tid * Bc + b];
    w[tid + 256] = wts[(size_t)(tid + 256) * Bc + b];
    __syncthreads();

    const int kk = tid & 63, sg = tid >> 6;
    const int k = kc * 64 + kk;

    const float* p = enc + ((size_t)(sg * 128) * Bc + b) * Hc + k;
    const float* wp = w + sg * 128;
    float acc = 0.0f;
#pragma unroll 8
    for (int s = 0; s < 128; s++)
        acc += wp[s] * p[(size_t)s * (Bc * Hc)];
    part[sg][kk] = acc;
    __syncthreads();

    if (tid < 64)
        g_ctx[(size_t)b * Hc + kc * 64 + tid] =
            (part[0][tid] + part[1][tid]) + (part[2][tid] + part[3][tid]);
}

// GRU gate combine: sums 8 gi partials (emb+ctx) and 4 gh partials (exact fp32).
__global__ void __launch_bounds__(256)
gru_kernel(const float* __restrict__ hidden, float* __restrict__ hnew,
           const float* __restrict__ bih, const float* __restrict__ bhh)
{
    const int g = blockIdx.x * 256 + threadIdx.x;   // 65536
    const int b = g >> 10, h = g & 1023;

    float gir = bih[h],            ghr = bhh[h];
    float giz = bih[Hc + h],       ghz = bhh[Hc + h];
    float gin = bih[2 * Hc + h],   ghn = bhh[2 * Hc + h];
#pragma unroll
    for (int z = 0; z < 8; z++) {
        const float* gi = g_gip + (size_t)(z * 64 + b) * (3 * Hc);
        gir += gi[h];
        giz += gi[Hc + h];
        gin += gi[2 * Hc + h];
    }
#pragma unroll
    for (int z = 0; z < 4; z++) {
        const float* gh = g_ghp + (size_t)(z * 64 + b) * (3 * Hc);
        ghr += gh[h];
        ghz += gh[Hc + h];
        ghn += gh[2 * Hc + h];
    }
    float r = 1.0f / (1.0f + expf(-(gir + ghr)));
    float z = 1.0f / (1.0f + expf(-(giz + ghz)));
    float n = tanhf(gin + r * ghn);
    float hp = hidden[g];
    hnew[g] = (1.0f - z) * n + z * hp;
}

// ===========================================================================
extern "C" void kernel_launch(void* const* d_in, const int* in_sizes, int n_in,
                              void* d_out, int out_size)
{
    const int*   input    = (const int*)d_in[0];
    const float* hidden   = (const float*)d_in[1];
    const float* enc      = (const float*)d_in[2];
    const float* emb      = (const float*)d_in[3];
    const float* attn_w_W = (const float*)d_in[4];
    const float* attn_w_b = (const float*)d_in[5];
    const float* attn_v_W = (const float*)d_in[6];
    // d_in[7] = attn_v_b : softmax-invariant, skipped
    const float* gru_Wih  = (const float*)d_in[8];
    const float* gru_Whh  = (const float*)d_in[9];
    const float* gru_bih  = (const float*)d_in[10];
    const float* gru_bhh  = (const float*)d_in[11];
    const float* out_W    = (const float*)d_in[12];
    const float* out_b    = (const float*)d_in[13];

    float* out    = (float*)d_out;
    float* logits = out;                        // B*V
    float* hnew   = out + (size_t)Bc * Vc;      // B*H
    float* wts    = hnew + (size_t)Bc * Hc;     // S*B

    float *p_hWhp, *p_ctx, *p_gip, *p_ghp;
    cudaGetSymbolAddress((void**)&p_hWhp, g_hWhp);
    cudaGetSymbolAddress((void**)&p_ctx,  g_ctx);
    cudaGetSymbolAddress((void**)&p_gip,  g_gip);
    cudaGetSymbolAddress((void**)&p_ghp,  g_ghp);

    cudaFuncSetAttribute(attn_score_tc, cudaFuncAttributeMaxDynamicSharedMemorySize, ATT_SMEM);
    cudaFuncSetAttribute(gemm_wact_tc,  cudaFuncAttributeMaxDynamicSharedMemorySize, LG_SMEM);

    // 0. convert enc + We to bf16
    convert_bf16<<<33792, 256>>>(enc, attn_w_W);
    // 1. hWh partials + gh partials + gi emb-half partials (exact fp32)
    splitk_pre<<<dim3(112, 1, 4), 256>>>(attn_w_W, hidden, gru_Whh, gru_Wih,
                                         emb, input, p_hWhp, p_ghp, p_gip);
    // 2. fused attention scores (bf16 tensor + fp32 tanh/v epilogue)
    attn_score_tc<<<dim3(8, 256), 128, ATT_SMEM>>>(attn_v_W, attn_w_b);
    // 3. softmax -> attn_weights (output region 3)
    softmax_kernel<<<Bc, 256>>>(wts);
    // 4. context (1024 CTAs) -> g_ctx
    ctx_kernel<<<dim3(16, Bc), 256>>>(enc, wts);
    // 5. gi ctx-half partials (exact fp32, K halved)
    splitk_gictx<<<dim3(48, 1, 4), 256>>>(gru_Wih, p_ctx,
                                          p_gip + (size_t)4 * 64 * 3 * Hc);
    // 6. GRU combine -> h_new (output region 2)
    gru_kernel<<<Bc * Hc / 256, 256>>>(hidden, hnew, gru_bih, gru_bhh);
    // 7. logits = h_new @ out_W^T + out_b (2-term split-tf32, output region 1)
    gemm_wact_tc<<<Vc / 128, 256, LG_SMEM>>>(out_W, Hc, hnew, logits, Vc, out_b);
}